// round 11
// baseline (speedup 1.0000x reference)
#include <cuda_runtime.h>
#include <cuda_fp16.h>
#include <math.h>
#include <stdint.h>

// ---------------- problem constants ----------------
#define B_   8
#define HH_  56
#define WW_  56
#define N_   (HH_*WW_)          // 3136
#define C_   512
#define NH_  16
#define HD_  32
#define WS_  7
#define WS2_ 49
#define HID_ 2048
#define TOK_ (B_*N_)            // 25088
#define THREEC_ (3*C_)          // 1536

// ---------------- scratch ----------------
static __device__ __half g_hh  [(size_t)TOK_*C_];
static __device__ __half g_qkvh[(size_t)TOK_*THREEC_];
static __device__ float  g_x1  [(size_t)TOK_*C_];
static __device__ __half g_h2h [(size_t)TOK_*HID_];
static __device__ __half g_h3h [(size_t)TOK_*HID_];
static __device__ __half g_wq  [(size_t)THREEC_*C_];
static __device__ __half g_wf1 [(size_t)HID_*C_];
static __device__ __half g_wf2 [(size_t)C_*HID_];

// ---------------- fp32 -> fp16 conversion ----------------
__global__ __launch_bounds__(256)
void f2h_kernel(const float4* __restrict__ in, __half2* __restrict__ out, int n4) {
    int i = blockIdx.x * 256 + threadIdx.x;
    if (i >= n4) return;
    float4 v = in[i];
    out[2 * i]     = __floats2half2_rn(v.x, v.y);
    out[2 * i + 1] = __floats2half2_rn(v.z, v.w);
}

// ---------------- LayerNorm: warp per row ----------------
__global__ __launch_bounds__(256)
void ln_kernel(const float* __restrict__ x, const float* __restrict__ g,
               const float* __restrict__ b, __half* __restrict__ out) {
    __shared__ float sg[C_], sb[C_];
    const int tid = threadIdx.x;
    sg[tid] = g[tid]; sg[tid + 256] = g[tid + 256];
    sb[tid] = b[tid]; sb[tid + 256] = b[tid + 256];
    __syncthreads();

    const int lane = tid & 31, wid = tid >> 5;
    const long row = (long)blockIdx.x * 8 + wid;
    const float4* xr = (const float4*)(x + row * C_);

    float4 v[4];
    float sum = 0.0f;
    #pragma unroll
    for (int k = 0; k < 4; ++k) {
        v[k] = xr[lane + k * 32];
        sum += v[k].x + v[k].y + v[k].z + v[k].w;
    }
    #pragma unroll
    for (int o = 16; o > 0; o >>= 1) sum += __shfl_xor_sync(0xffffffffu, sum, o);
    float mu = sum * (1.0f / C_);

    float vs = 0.0f;
    #pragma unroll
    for (int k = 0; k < 4; ++k) {
        float dx = v[k].x - mu, dy = v[k].y - mu, dz = v[k].z - mu, dw = v[k].w - mu;
        vs += dx * dx + dy * dy + dz * dz + dw * dw;
    }
    #pragma unroll
    for (int o = 16; o > 0; o >>= 1) vs += __shfl_xor_sync(0xffffffffu, vs, o);
    float inv = rsqrtf(vs * (1.0f / C_) + 1e-5f);

    __half2* orow = (__half2*)(out + row * C_);
    #pragma unroll
    for (int k = 0; k < 4; ++k) {
        int i4 = lane + k * 32, c = i4 * 4;
        float e0 = (v[k].x - mu) * inv * sg[c]     + sb[c];
        float e1 = (v[k].y - mu) * inv * sg[c + 1] + sb[c + 1];
        float e2 = (v[k].z - mu) * inv * sg[c + 2] + sb[c + 2];
        float e3 = (v[k].w - mu) * inv * sg[c + 3] + sb[c + 3];
        orow[i4 * 2]     = __floats2half2_rn(e0, e1);
        orow[i4 * 2 + 1] = __floats2half2_rn(e2, e3);
    }
}

// ---------------- FP16 GEMM: 128x128 CTA, 4 warps 64x64, 3-stage (R6) + cg ----------
#define BM 128
#define BN 128
#define BKH 32
#define LST 40
#define STAGEH ((BM + BN) * LST)
#define GSMEM (3 * STAGEH * 2)

__device__ __forceinline__ void cpa16(uint32_t s, const void* g) {
    asm volatile("cp.async.cg.shared.global [%0], [%1], 16;" :: "r"(s), "l"(g));
}
__device__ __forceinline__ void ldsm4(uint32_t* r, uint32_t addr) {
    asm volatile("ldmatrix.sync.aligned.m8n8.x4.shared.b16 {%0,%1,%2,%3}, [%4];"
                 : "=r"(r[0]), "=r"(r[1]), "=r"(r[2]), "=r"(r[3]) : "r"(addr));
}
__device__ __forceinline__ void mma_f16(float* c, const uint32_t* a, const uint32_t* b) {
    asm volatile(
        "mma.sync.aligned.m16n8k16.row.col.f32.f16.f16.f32 "
        "{%0,%1,%2,%3}, {%4,%5,%6,%7}, {%8,%9}, {%0,%1,%2,%3};"
        : "+f"(c[0]), "+f"(c[1]), "+f"(c[2]), "+f"(c[3])
        : "r"(a[0]), "r"(a[1]), "r"(a[2]), "r"(a[3]), "r"(b[0]), "r"(b[1]));
}

template<bool OUT_HALF, bool HAS_RES>
__global__ __launch_bounds__(128, 2)
void gemm_h_kernel(const __half* __restrict__ A, const __half* __restrict__ Bm,
                   const float* __restrict__ bias, const float* __restrict__ res,
                   void* __restrict__ outv, int M, int N, int K) {
    extern __shared__ __half sm[];
    const uint32_t smb = (uint32_t)__cvta_generic_to_shared(sm);
    const int tid = threadIdx.x;
    const int lane = tid & 31, wid = tid >> 5;
    const int wm = wid & 1, wn = wid >> 1;
    const int g8 = lane >> 2, tig = lane & 3;
    const int m0 = blockIdx.y * BM, n0 = blockIdx.x * BN;

    float acc[4][8][4];
    #pragma unroll
    for (int i = 0; i < 4; ++i)
        #pragma unroll
        for (int j = 0; j < 8; ++j)
            #pragma unroll
            for (int t = 0; t < 4; ++t) acc[i][j][t] = 0.0f;

    const int T = K / BKH;
    const int lrow = tid >> 2, lq = tid & 3;

    auto load_stage = [&](int t, int s) {
        const int k0 = t * BKH;
        #pragma unroll
        for (int i = 0; i < 4; ++i) {
            int row = lrow + i * 32;
            uint32_t sa = smb + (uint32_t)(s * STAGEH + row * LST + lq * 8) * 2u;
            cpa16(sa, A + (long)(m0 + row) * K + k0 + lq * 8);
            cpa16(sa + BM * LST * 2u, Bm + (long)(n0 + row) * K + k0 + lq * 8);
        }
    };

    load_stage(0, 0);
    asm volatile("cp.async.commit_group;");
    if (T > 1) { load_stage(1, 1); asm volatile("cp.async.commit_group;"); }

    const int a_r = (lane & 15), a_k = (lane >> 4) * 8;
    const int b_r = (lane & 7), b_t = (lane >> 4), b_k = ((lane >> 3) & 1) * 8;

    for (int t = 0; t < T; ++t) {
        const int s = t % 3;
        if (t + 2 < T) {
            load_stage(t + 2, (t + 2) % 3);
            asm volatile("cp.async.commit_group;");
            asm volatile("cp.async.wait_group 2;");
        } else if (t + 1 < T) {
            asm volatile("cp.async.wait_group 1;");
        } else {
            asm volatile("cp.async.wait_group 0;");
        }
        __syncthreads();

        const uint32_t sA = smb + (uint32_t)(s * STAGEH) * 2u;
        const uint32_t sB = sA + BM * LST * 2u;

        #pragma unroll
        for (int kk = 0; kk < 2; ++kk) {
            const int kb = kk * 16;
            uint32_t a[4][4], b[8][2];
            #pragma unroll
            for (int i = 0; i < 4; ++i)
                ldsm4(a[i], sA + (uint32_t)((wm * 64 + i * 16 + a_r) * LST + kb + a_k) * 2u);
            #pragma unroll
            for (int jp = 0; jp < 4; ++jp) {
                uint32_t r[4];
                ldsm4(r, sB + (uint32_t)((wn * 64 + (jp * 2 + b_t) * 8 + b_r) * LST + kb + b_k) * 2u);
                b[jp * 2][0] = r[0]; b[jp * 2][1] = r[1];
                b[jp * 2 + 1][0] = r[2]; b[jp * 2 + 1][1] = r[3];
            }
            #pragma unroll
            for (int i = 0; i < 4; ++i)
                #pragma unroll
                for (int j = 0; j < 8; ++j) mma_f16(acc[i][j], a[i], b[j]);
        }
        __syncthreads();
    }

    // epilogue
    #pragma unroll
    for (int i = 0; i < 4; ++i) {
        int r = m0 + wm * 64 + i * 16 + g8;
        #pragma unroll
        for (int j = 0; j < 8; ++j) {
            int n = n0 + wn * 64 + j * 8 + tig * 2;
            float b0 = bias[n], b1 = bias[n + 1];
            float v0 = acc[i][j][0] + b0, v1 = acc[i][j][1] + b1;
            float v2 = acc[i][j][2] + b0, v3 = acc[i][j][3] + b1;
            long o0 = (long)r * N + n;
            long o1 = (long)(r + 8) * N + n;
            if (HAS_RES) {
                float2 r0 = *(const float2*)(res + o0);
                float2 r1 = *(const float2*)(res + o1);
                v0 += r0.x; v1 += r0.y; v2 += r1.x; v3 += r1.y;
            }
            if (OUT_HALF) {
                __half* out = (__half*)outv;
                *(__half2*)(out + o0) = __floats2half2_rn(v0, v1);
                *(__half2*)(out + o1) = __floats2half2_rn(v2, v3);
            } else {
                float* out = (float*)outv;
                *(float2*)(out + o0) = make_float2(v0, v1);
                *(float2*)(out + o1) = make_float2(v2, v3);
            }
        }
    }
}

// ---------------- Windowed attention (R6 proven version) ----------------------------
__global__ __launch_bounds__(256)
void attn_kernel(const __half* __restrict__ qkv, const float* __restrict__ rpb,
                 const float* __restrict__ x, float* __restrict__ x1) {
    const int head = blockIdx.x & 15;
    const int win  = blockIdx.x >> 4;
    const int b    = win >> 6;
    const int wi   = (win >> 3) & 7;
    const int wj   = win & 7;
    const int tid  = threadIdx.x;

    __shared__ float q[WS2_][HD_ + 1];
    __shared__ float k[WS2_][HD_ + 1];
    __shared__ float v[WS2_][HD_ + 1];
    __shared__ float s[WS2_][WS2_ + 1];

    for (int idx = tid; idx < WS2_ * 16; idx += 256) {
        int p = idx >> 4, d2 = idx & 15;
        int token = (wi * 7 + p / 7) * 56 + (wj * 7 + p % 7);
        long base = ((long)b * N_ + token) * THREEC_ + head * HD_ + 2 * d2;
        float2 fq = __half22float2(*(const __half2*)(qkv + base));
        float2 fk = __half22float2(*(const __half2*)(qkv + base + C_));
        float2 fv = __half22float2(*(const __half2*)(qkv + base + 2 * C_));
        q[p][2 * d2] = fq.x; q[p][2 * d2 + 1] = fq.y;
        k[p][2 * d2] = fk.x; k[p][2 * d2 + 1] = fk.y;
        v[p][2 * d2] = fv.x; v[p][2 * d2 + 1] = fv.y;
    }
    __syncthreads();

    const float scale = 0.17677669529663687f;
    for (int idx = tid; idx < WS2_ * WS2_; idx += 256) {
        int i = idx / WS2_, j = idx - i * WS2_;
        float acc = 0.0f;
        #pragma unroll
        for (int d = 0; d < HD_; ++d) acc = fmaf(q[i][d], k[j][d], acc);
        int dpi = (i / 7) - (j / 7) + 6;
        int dpj = (i % 7) - (j % 7) + 6;
        s[i][j] = acc * scale + rpb[(dpi * 13 + dpj) * NH_ + head];
    }
    __syncthreads();

    if (tid < WS2_) {
        float mx = -1e30f;
        #pragma unroll
        for (int j = 0; j < WS2_; ++j) mx = fmaxf(mx, s[tid][j]);
        float sum = 0.0f;
        #pragma unroll
        for (int j = 0; j < WS2_; ++j) { float e = __expf(s[tid][j] - mx); s[tid][j] = e; sum += e; }
        float inv = 1.0f / sum;
        #pragma unroll
        for (int j = 0; j < WS2_; ++j) s[tid][j] *= inv;
    }
    __syncthreads();

    for (int idx = tid; idx < WS2_ * HD_; idx += 256) {
        int i = idx >> 5, d = idx & 31;
        float acc = 0.0f;
        #pragma unroll
        for (int j = 0; j < WS2_; ++j) acc = fmaf(s[i][j], v[j][d], acc);
        int token = (wi * 7 + i / 7) * 56 + (wj * 7 + i % 7);
        long o = ((long)b * N_ + token) * C_ + head * HD_ + d;
        x1[o] = x[o] + acc;
    }
}

// ---------------- depthwise 3x3 + GELU: row-sweep ----------------
__global__ __launch_bounds__(256)
void dwconv_gelu_kernel(const __half2* __restrict__ h2, const float* __restrict__ w,
                        const float* __restrict__ bias, __half2* __restrict__ out) {
    __shared__ float ws[512 * 9];
    const int bid = blockIdx.x;
    const int chunk = bid & 3;
    const int hrow = (bid >> 2) % 56;
    const int bb = (bid >> 2) / 56;
    const int cp = chunk * 256 + threadIdx.x;

    for (int q = threadIdx.x; q < 512 * 9; q += 256)
        ws[q] = w[(long)(chunk * 512) * 9 + q];
    __syncthreads();

    const float* w0 = &ws[(2 * threadIdx.x) * 9];
    const float* w1 = w0 + 9;
    const int c = cp * 2;
    const float bi0 = bias[c], bi1 = bias[c + 1];

    const bool up = (hrow > 0), dn = (hrow < 55);
    const long rbase = (((long)bb * 56 + hrow) * 56) * 1024 + cp;
    const long rup = rbase - 56 * 1024, rdn = rbase + 56 * 1024;

    float2 col[3][3];
    #pragma unroll
    for (int j = 0; j < 3; ++j)
        #pragma unroll
        for (int dy = 0; dy < 3; ++dy) col[j][dy] = make_float2(0.f, 0.f);

    col[1][0] = up ? __half22float2(h2[rup]) : make_float2(0.f, 0.f);
    col[1][1] = __half22float2(h2[rbase]);
    col[1][2] = dn ? __half22float2(h2[rdn]) : make_float2(0.f, 0.f);

    for (int wcol = 0; wcol < 56; ++wcol) {
        if (wcol + 1 < 56) {
            long o = (long)(wcol + 1) * 1024;
            col[2][0] = up ? __half22float2(h2[rup + o]) : make_float2(0.f, 0.f);
            col[2][1] = __half22float2(h2[rbase + o]);
            col[2][2] = dn ? __half22float2(h2[rdn + o]) : make_float2(0.f, 0.f);
        } else {
            col[2][0] = col[2][1] = col[2][2] = make_float2(0.f, 0.f);
        }

        float a0 = bi0, a1 = bi1;
        #pragma unroll
        for (int dy = 0; dy < 3; ++dy) {
            #pragma unroll
            for (int dx = 0; dx < 3; ++dx) {
                float2 vv = col[dx][dy];
                a0 = fmaf(vv.x, w0[dy * 3 + dx], a0);
                a1 = fmaf(vv.y, w1[dy * 3 + dx], a1);
            }
        }
        float g0 = 0.5f * a0 * (1.0f + erff(a0 * 0.70710678118654752f));
        float g1 = 0.5f * a1 * (1.0f + erff(a1 * 0.70710678118654752f));
        out[rbase + (long)wcol * 1024] = __floats2half2_rn(g0, g1);

        #pragma unroll
        for (int dy = 0; dy < 3; ++dy) { col[0][dy] = col[1][dy]; col[1][dy] = col[2][dy]; }
    }
}

// ---------------- launch ----------------
extern "C" void kernel_launch(void* const* d_in, const int* in_sizes, int n_in,
                              void* d_out, int out_size) {
    const float* x       = (const float*)d_in[0];
    const float* norm1_g = (const float*)d_in[3];
    const float* norm1_b = (const float*)d_in[4];
    const float* norm2_g = (const float*)d_in[5];
    const float* norm2_b = (const float*)d_in[6];
    const float* qkv_w   = (const float*)d_in[7];
    const float* qkv_b   = (const float*)d_in[8];
    const float* rpb     = (const float*)d_in[9];
    const float* fc1_w   = (const float*)d_in[10];
    const float* fc1_b   = (const float*)d_in[11];
    const float* dw_w    = (const float*)d_in[12];
    const float* dw_b    = (const float*)d_in[13];
    const float* fc2_w   = (const float*)d_in[14];
    const float* fc2_b   = (const float*)d_in[15];
    float* out = (float*)d_out;

    __half *p_hh, *p_qkvh, *p_h2h, *p_h3h, *p_wq, *p_wf1, *p_wf2;
    float *p_x1;
    cudaGetSymbolAddress((void**)&p_hh,   g_hh);
    cudaGetSymbolAddress((void**)&p_qkvh, g_qkvh);
    cudaGetSymbolAddress((void**)&p_x1,   g_x1);
    cudaGetSymbolAddress((void**)&p_h2h,  g_h2h);
    cudaGetSymbolAddress((void**)&p_h3h,  g_h3h);
    cudaGetSymbolAddress((void**)&p_wq,   g_wq);
    cudaGetSymbolAddress((void**)&p_wf1,  g_wf1);
    cudaGetSymbolAddress((void**)&p_wf2,  g_wf2);

    cudaFuncSetAttribute(gemm_h_kernel<true, false>,
                         cudaFuncAttributeMaxDynamicSharedMemorySize, GSMEM);
    cudaFuncSetAttribute(gemm_h_kernel<false, true>,
                         cudaFuncAttributeMaxDynamicSharedMemorySize, GSMEM);

    // 0) weight conversions
    f2h_kernel<<<(THREEC_ * C_ / 4 + 255) / 256, 256>>>((const float4*)qkv_w, (__half2*)p_wq, THREEC_ * C_ / 4);
    f2h_kernel<<<(HID_ * C_ / 4 + 255) / 256, 256>>>((const float4*)fc1_w, (__half2*)p_wf1, HID_ * C_ / 4);
    f2h_kernel<<<(C_ * HID_ / 4 + 255) / 256, 256>>>((const float4*)fc2_w, (__half2*)p_wf2, C_ * HID_ / 4);

    // 1) LN1
    ln_kernel<<<TOK_ / 8, 256>>>(x, norm1_g, norm1_b, p_hh);
    // 2) QKV GEMM
    gemm_h_kernel<true, false><<<dim3(THREEC_ / BN, TOK_ / BM), 128, GSMEM>>>(
        p_hh, p_wq, qkv_b, nullptr, p_qkvh, TOK_, THREEC_, C_);
    // 3) windowed attention + residual
    attn_kernel<<<B_ * 64 * NH_, 256>>>(p_qkvh, rpb, x, p_x1);
    // 4) LN2
    ln_kernel<<<TOK_ / 8, 256>>>(p_x1, norm2_g, norm2_b, p_hh);
    // 5) fc1 GEMM
    gemm_h_kernel<true, false><<<dim3(HID_ / BN, TOK_ / BM), 128, GSMEM>>>(
        p_hh, p_wf1, fc1_b, nullptr, p_h2h, TOK_, HID_, C_);
    // 6) depthwise conv + GELU
    dwconv_gelu_kernel<<<B_ * HH_ * 4, 256>>>(
        (const __half2*)p_h2h, dw_w, dw_b, (__half2*)p_h3h);
    // 7) fc2 GEMM + residual -> out
    gemm_h_kernel<false, true><<<dim3(C_ / BN, TOK_ / BM), 128, GSMEM>>>(
        p_h3h, p_wf2, fc2_b, p_x1, out, TOK_, C_, HID_);
}

// round 12
// speedup vs baseline: 1.0523x; 1.0523x over previous
#include <cuda_runtime.h>
#include <cuda_fp16.h>
#include <math.h>
#include <stdint.h>

// ---------------- problem constants ----------------
#define B_   8
#define HH_  56
#define WW_  56
#define N_   (HH_*WW_)          // 3136
#define C_   512
#define NH_  16
#define HD_  32
#define WS_  7
#define WS2_ 49
#define HID_ 2048
#define TOK_ (B_*N_)            // 25088
#define THREEC_ (3*C_)          // 1536

// ---------------- scratch ----------------
static __device__ __half g_hh  [(size_t)TOK_*C_];
static __device__ __half g_qkvh[(size_t)TOK_*THREEC_];
static __device__ float  g_x1  [(size_t)TOK_*C_];
static __device__ __half g_h2h [(size_t)TOK_*HID_];
static __device__ __half g_h3h [(size_t)TOK_*HID_];
static __device__ __half g_wq  [(size_t)THREEC_*C_];
static __device__ __half g_wf1 [(size_t)HID_*C_];
static __device__ __half g_wf2 [(size_t)C_*HID_];

// ---------------- fp32 -> fp16 conversion ----------------
__global__ __launch_bounds__(256)
void f2h_kernel(const float4* __restrict__ in, __half2* __restrict__ out, int n4) {
    int i = blockIdx.x * 256 + threadIdx.x;
    if (i >= n4) return;
    float4 v = in[i];
    out[2 * i]     = __floats2half2_rn(v.x, v.y);
    out[2 * i + 1] = __floats2half2_rn(v.z, v.w);
}

// ---------------- LayerNorm: warp per row ----------------
__global__ __launch_bounds__(256)
void ln_kernel(const float* __restrict__ x, const float* __restrict__ g,
               const float* __restrict__ b, __half* __restrict__ out) {
    __shared__ float sg[C_], sb[C_];
    const int tid = threadIdx.x;
    sg[tid] = g[tid]; sg[tid + 256] = g[tid + 256];
    sb[tid] = b[tid]; sb[tid + 256] = b[tid + 256];
    __syncthreads();

    const int lane = tid & 31, wid = tid >> 5;
    const long row = (long)blockIdx.x * 8 + wid;
    const float4* xr = (const float4*)(x + row * C_);

    float4 v[4];
    float sum = 0.0f;
    #pragma unroll
    for (int k = 0; k < 4; ++k) {
        v[k] = xr[lane + k * 32];
        sum += v[k].x + v[k].y + v[k].z + v[k].w;
    }
    #pragma unroll
    for (int o = 16; o > 0; o >>= 1) sum += __shfl_xor_sync(0xffffffffu, sum, o);
    float mu = sum * (1.0f / C_);

    float vs = 0.0f;
    #pragma unroll
    for (int k = 0; k < 4; ++k) {
        float dx = v[k].x - mu, dy = v[k].y - mu, dz = v[k].z - mu, dw = v[k].w - mu;
        vs += dx * dx + dy * dy + dz * dz + dw * dw;
    }
    #pragma unroll
    for (int o = 16; o > 0; o >>= 1) vs += __shfl_xor_sync(0xffffffffu, vs, o);
    float inv = rsqrtf(vs * (1.0f / C_) + 1e-5f);

    __half2* orow = (__half2*)(out + row * C_);
    #pragma unroll
    for (int k = 0; k < 4; ++k) {
        int i4 = lane + k * 32, c = i4 * 4;
        float e0 = (v[k].x - mu) * inv * sg[c]     + sb[c];
        float e1 = (v[k].y - mu) * inv * sg[c + 1] + sb[c + 1];
        float e2 = (v[k].z - mu) * inv * sg[c + 2] + sb[c + 2];
        float e3 = (v[k].w - mu) * inv * sg[c + 3] + sb[c + 3];
        orow[i4 * 2]     = __floats2half2_rn(e0, e1);
        orow[i4 * 2 + 1] = __floats2half2_rn(e2, e3);
    }
}

// ---------------- FP16 GEMM: 128x128 CTA, 4 warps 64x64, 3-stage (R6 exact) ---------
#define BM 128
#define BN 128
#define BKH 32
#define LST 40
#define STAGEH ((BM + BN) * LST)
#define GSMEM (3 * STAGEH * 2)

__device__ __forceinline__ void cpa16(uint32_t s, const void* g) {
    asm volatile("cp.async.ca.shared.global [%0], [%1], 16;" :: "r"(s), "l"(g));
}
__device__ __forceinline__ void ldsm4(uint32_t* r, uint32_t addr) {
    asm volatile("ldmatrix.sync.aligned.m8n8.x4.shared.b16 {%0,%1,%2,%3}, [%4];"
                 : "=r"(r[0]), "=r"(r[1]), "=r"(r[2]), "=r"(r[3]) : "r"(addr));
}
__device__ __forceinline__ void mma_f16(float* c, const uint32_t* a, const uint32_t* b) {
    asm volatile(
        "mma.sync.aligned.m16n8k16.row.col.f32.f16.f16.f32 "
        "{%0,%1,%2,%3}, {%4,%5,%6,%7}, {%8,%9}, {%0,%1,%2,%3};"
        : "+f"(c[0]), "+f"(c[1]), "+f"(c[2]), "+f"(c[3])
        : "r"(a[0]), "r"(a[1]), "r"(a[2]), "r"(a[3]), "r"(b[0]), "r"(b[1]));
}

template<bool OUT_HALF, bool HAS_RES>
__global__ __launch_bounds__(128, 2)
void gemm_h_kernel(const __half* __restrict__ A, const __half* __restrict__ Bm,
                   const float* __restrict__ bias, const float* __restrict__ res,
                   void* __restrict__ outv, int M, int N, int K) {
    extern __shared__ __half sm[];
    const uint32_t smb = (uint32_t)__cvta_generic_to_shared(sm);
    const int tid = threadIdx.x;
    const int lane = tid & 31, wid = tid >> 5;
    const int wm = wid & 1, wn = wid >> 1;
    const int g8 = lane >> 2, tig = lane & 3;
    const int m0 = blockIdx.y * BM, n0 = blockIdx.x * BN;

    float acc[4][8][4];
    #pragma unroll
    for (int i = 0; i < 4; ++i)
        #pragma unroll
        for (int j = 0; j < 8; ++j)
            #pragma unroll
            for (int t = 0; t < 4; ++t) acc[i][j][t] = 0.0f;

    const int T = K / BKH;
    const int lrow = tid >> 2, lq = tid & 3;

    auto load_stage = [&](int t, int s) {
        const int k0 = t * BKH;
        #pragma unroll
        for (int i = 0; i < 4; ++i) {
            int row = lrow + i * 32;
            uint32_t sa = smb + (uint32_t)(s * STAGEH + row * LST + lq * 8) * 2u;
            cpa16(sa, A + (long)(m0 + row) * K + k0 + lq * 8);
            cpa16(sa + BM * LST * 2u, Bm + (long)(n0 + row) * K + k0 + lq * 8);
        }
    };

    load_stage(0, 0);
    asm volatile("cp.async.commit_group;");
    if (T > 1) { load_stage(1, 1); asm volatile("cp.async.commit_group;"); }

    const int a_r = (lane & 15), a_k = (lane >> 4) * 8;
    const int b_r = (lane & 7), b_t = (lane >> 4), b_k = ((lane >> 3) & 1) * 8;

    for (int t = 0; t < T; ++t) {
        const int s = t % 3;
        if (t + 2 < T) {
            load_stage(t + 2, (t + 2) % 3);
            asm volatile("cp.async.commit_group;");
            asm volatile("cp.async.wait_group 2;");
        } else if (t + 1 < T) {
            asm volatile("cp.async.wait_group 1;");
        } else {
            asm volatile("cp.async.wait_group 0;");
        }
        __syncthreads();

        const uint32_t sA = smb + (uint32_t)(s * STAGEH) * 2u;
        const uint32_t sB = sA + BM * LST * 2u;

        #pragma unroll
        for (int kk = 0; kk < 2; ++kk) {
            const int kb = kk * 16;
            uint32_t a[4][4], b[8][2];
            #pragma unroll
            for (int i = 0; i < 4; ++i)
                ldsm4(a[i], sA + (uint32_t)((wm * 64 + i * 16 + a_r) * LST + kb + a_k) * 2u);
            #pragma unroll
            for (int jp = 0; jp < 4; ++jp) {
                uint32_t r[4];
                ldsm4(r, sB + (uint32_t)((wn * 64 + (jp * 2 + b_t) * 8 + b_r) * LST + kb + b_k) * 2u);
                b[jp * 2][0] = r[0]; b[jp * 2][1] = r[1];
                b[jp * 2 + 1][0] = r[2]; b[jp * 2 + 1][1] = r[3];
            }
            #pragma unroll
            for (int i = 0; i < 4; ++i)
                #pragma unroll
                for (int j = 0; j < 8; ++j) mma_f16(acc[i][j], a[i], b[j]);
        }
        __syncthreads();
    }

    // epilogue
    #pragma unroll
    for (int i = 0; i < 4; ++i) {
        int r = m0 + wm * 64 + i * 16 + g8;
        #pragma unroll
        for (int j = 0; j < 8; ++j) {
            int n = n0 + wn * 64 + j * 8 + tig * 2;
            float b0 = bias[n], b1 = bias[n + 1];
            float v0 = acc[i][j][0] + b0, v1 = acc[i][j][1] + b1;
            float v2 = acc[i][j][2] + b0, v3 = acc[i][j][3] + b1;
            long o0 = (long)r * N + n;
            long o1 = (long)(r + 8) * N + n;
            if (HAS_RES) {
                float2 r0 = *(const float2*)(res + o0);
                float2 r1 = *(const float2*)(res + o1);
                v0 += r0.x; v1 += r0.y; v2 += r1.x; v3 += r1.y;
            }
            if (OUT_HALF) {
                __half* out = (__half*)outv;
                *(__half2*)(out + o0) = __floats2half2_rn(v0, v1);
                *(__half2*)(out + o1) = __floats2half2_rn(v2, v3);
            } else {
                float* out = (float*)outv;
                *(float2*)(out + o0) = make_float2(v0, v1);
                *(float2*)(out + o1) = make_float2(v2, v3);
            }
        }
    }
}

// ---------------- Windowed attention (R6 proven version) ----------------------------
__global__ __launch_bounds__(256)
void attn_kernel(const __half* __restrict__ qkv, const float* __restrict__ rpb,
                 const float* __restrict__ x, float* __restrict__ x1) {
    const int head = blockIdx.x & 15;
    const int win  = blockIdx.x >> 4;
    const int b    = win >> 6;
    const int wi   = (win >> 3) & 7;
    const int wj   = win & 7;
    const int tid  = threadIdx.x;

    __shared__ float q[WS2_][HD_ + 1];
    __shared__ float k[WS2_][HD_ + 1];
    __shared__ float v[WS2_][HD_ + 1];
    __shared__ float s[WS2_][WS2_ + 1];

    for (int idx = tid; idx < WS2_ * 16; idx += 256) {
        int p = idx >> 4, d2 = idx & 15;
        int token = (wi * 7 + p / 7) * 56 + (wj * 7 + p % 7);
        long base = ((long)b * N_ + token) * THREEC_ + head * HD_ + 2 * d2;
        float2 fq = __half22float2(*(const __half2*)(qkv + base));
        float2 fk = __half22float2(*(const __half2*)(qkv + base + C_));
        float2 fv = __half22float2(*(const __half2*)(qkv + base + 2 * C_));
        q[p][2 * d2] = fq.x; q[p][2 * d2 + 1] = fq.y;
        k[p][2 * d2] = fk.x; k[p][2 * d2 + 1] = fk.y;
        v[p][2 * d2] = fv.x; v[p][2 * d2 + 1] = fv.y;
    }
    __syncthreads();

    const float scale = 0.17677669529663687f;
    for (int idx = tid; idx < WS2_ * WS2_; idx += 256) {
        int i = idx / WS2_, j = idx - i * WS2_;
        float acc = 0.0f;
        #pragma unroll
        for (int d = 0; d < HD_; ++d) acc = fmaf(q[i][d], k[j][d], acc);
        int dpi = (i / 7) - (j / 7) + 6;
        int dpj = (i % 7) - (j % 7) + 6;
        s[i][j] = acc * scale + rpb[(dpi * 13 + dpj) * NH_ + head];
    }
    __syncthreads();

    if (tid < WS2_) {
        float mx = -1e30f;
        #pragma unroll
        for (int j = 0; j < WS2_; ++j) mx = fmaxf(mx, s[tid][j]);
        float sum = 0.0f;
        #pragma unroll
        for (int j = 0; j < WS2_; ++j) { float e = __expf(s[tid][j] - mx); s[tid][j] = e; sum += e; }
        float inv = 1.0f / sum;
        #pragma unroll
        for (int j = 0; j < WS2_; ++j) s[tid][j] *= inv;
    }
    __syncthreads();

    for (int idx = tid; idx < WS2_ * HD_; idx += 256) {
        int i = idx >> 5, d = idx & 31;
        float acc = 0.0f;
        #pragma unroll
        for (int j = 0; j < WS2_; ++j) acc = fmaf(s[i][j], v[j][d], acc);
        int token = (wi * 7 + i / 7) * 56 + (wj * 7 + i % 7);
        long o = ((long)b * N_ + token) * C_ + head * HD_ + d;
        x1[o] = x[o] + acc;
    }
}

// ---------------- depthwise 3x3 + GELU: row-sweep ----------------
__global__ __launch_bounds__(256)
void dwconv_gelu_kernel(const __half2* __restrict__ h2, const float* __restrict__ w,
                        const float* __restrict__ bias, __half2* __restrict__ out) {
    __shared__ float ws[512 * 9];
    const int bid = blockIdx.x;
    const int chunk = bid & 3;
    const int hrow = (bid >> 2) % 56;
    const int bb = (bid >> 2) / 56;
    const int cp = chunk * 256 + threadIdx.x;

    for (int q = threadIdx.x; q < 512 * 9; q += 256)
        ws[q] = w[(long)(chunk * 512) * 9 + q];
    __syncthreads();

    const float* w0 = &ws[(2 * threadIdx.x) * 9];
    const float* w1 = w0 + 9;
    const int c = cp * 2;
    const float bi0 = bias[c], bi1 = bias[c + 1];

    const bool up = (hrow > 0), dn = (hrow < 55);
    const long rbase = (((long)bb * 56 + hrow) * 56) * 1024 + cp;
    const long rup = rbase - 56 * 1024, rdn = rbase + 56 * 1024;

    float2 col[3][3];
    #pragma unroll
    for (int j = 0; j < 3; ++j)
        #pragma unroll
        for (int dy = 0; dy < 3; ++dy) col[j][dy] = make_float2(0.f, 0.f);

    col[1][0] = up ? __half22float2(h2[rup]) : make_float2(0.f, 0.f);
    col[1][1] = __half22float2(h2[rbase]);
    col[1][2] = dn ? __half22float2(h2[rdn]) : make_float2(0.f, 0.f);

    for (int wcol = 0; wcol < 56; ++wcol) {
        if (wcol + 1 < 56) {
            long o = (long)(wcol + 1) * 1024;
            col[2][0] = up ? __half22float2(h2[rup + o]) : make_float2(0.f, 0.f);
            col[2][1] = __half22float2(h2[rbase + o]);
            col[2][2] = dn ? __half22float2(h2[rdn + o]) : make_float2(0.f, 0.f);
        } else {
            col[2][0] = col[2][1] = col[2][2] = make_float2(0.f, 0.f);
        }

        float a0 = bi0, a1 = bi1;
        #pragma unroll
        for (int dy = 0; dy < 3; ++dy) {
            #pragma unroll
            for (int dx = 0; dx < 3; ++dx) {
                float2 vv = col[dx][dy];
                a0 = fmaf(vv.x, w0[dy * 3 + dx], a0);
                a1 = fmaf(vv.y, w1[dy * 3 + dx], a1);
            }
        }
        float g0 = 0.5f * a0 * (1.0f + erff(a0 * 0.70710678118654752f));
        float g1 = 0.5f * a1 * (1.0f + erff(a1 * 0.70710678118654752f));
        out[rbase + (long)wcol * 1024] = __floats2half2_rn(g0, g1);

        #pragma unroll
        for (int dy = 0; dy < 3; ++dy) { col[0][dy] = col[1][dy]; col[1][dy] = col[2][dy]; }
    }
}

// ---------------- launch ----------------
extern "C" void kernel_launch(void* const* d_in, const int* in_sizes, int n_in,
                              void* d_out, int out_size) {
    const float* x       = (const float*)d_in[0];
    const float* norm1_g = (const float*)d_in[3];
    const float* norm1_b = (const float*)d_in[4];
    const float* norm2_g = (const float*)d_in[5];
    const float* norm2_b = (const float*)d_in[6];
    const float* qkv_w   = (const float*)d_in[7];
    const float* qkv_b   = (const float*)d_in[8];
    const float* rpb     = (const float*)d_in[9];
    const float* fc1_w   = (const float*)d_in[10];
    const float* fc1_b   = (const float*)d_in[11];
    const float* dw_w    = (const float*)d_in[12];
    const float* dw_b    = (const float*)d_in[13];
    const float* fc2_w   = (const float*)d_in[14];
    const float* fc2_b   = (const float*)d_in[15];
    float* out = (float*)d_out;

    __half *p_hh, *p_qkvh, *p_h2h, *p_h3h, *p_wq, *p_wf1, *p_wf2;
    float *p_x1;
    cudaGetSymbolAddress((void**)&p_hh,   g_hh);
    cudaGetSymbolAddress((void**)&p_qkvh, g_qkvh);
    cudaGetSymbolAddress((void**)&p_x1,   g_x1);
    cudaGetSymbolAddress((void**)&p_h2h,  g_h2h);
    cudaGetSymbolAddress((void**)&p_h3h,  g_h3h);
    cudaGetSymbolAddress((void**)&p_wq,   g_wq);
    cudaGetSymbolAddress((void**)&p_wf1,  g_wf1);
    cudaGetSymbolAddress((void**)&p_wf2,  g_wf2);

    cudaFuncSetAttribute(gemm_h_kernel<true, false>,
                         cudaFuncAttributeMaxDynamicSharedMemorySize, GSMEM);
    cudaFuncSetAttribute(gemm_h_kernel<false, true>,
                         cudaFuncAttributeMaxDynamicSharedMemorySize, GSMEM);

    // 0) weight conversions
    f2h_kernel<<<(THREEC_ * C_ / 4 + 255) / 256, 256>>>((const float4*)qkv_w, (__half2*)p_wq, THREEC_ * C_ / 4);
    f2h_kernel<<<(HID_ * C_ / 4 + 255) / 256, 256>>>((const float4*)fc1_w, (__half2*)p_wf1, HID_ * C_ / 4);
    f2h_kernel<<<(C_ * HID_ / 4 + 255) / 256, 256>>>((const float4*)fc2_w, (__half2*)p_wf2, C_ * HID_ / 4);

    // 1) LN1
    ln_kernel<<<TOK_ / 8, 256>>>(x, norm1_g, norm1_b, p_hh);
    // 2) QKV GEMM
    gemm_h_kernel<true, false><<<dim3(THREEC_ / BN, TOK_ / BM), 128, GSMEM>>>(
        p_hh, p_wq, qkv_b, nullptr, p_qkvh, TOK_, THREEC_, C_);
    // 3) windowed attention + residual
    attn_kernel<<<B_ * 64 * NH_, 256>>>(p_qkvh, rpb, x, p_x1);
    // 4) LN2
    ln_kernel<<<TOK_ / 8, 256>>>(p_x1, norm2_g, norm2_b, p_hh);
    // 5) fc1 GEMM
    gemm_h_kernel<true, false><<<dim3(HID_ / BN, TOK_ / BM), 128, GSMEM>>>(
        p_hh, p_wf1, fc1_b, nullptr, p_h2h, TOK_, HID_, C_);
    // 6) depthwise conv + GELU
    dwconv_gelu_kernel<<<B_ * HH_ * 4, 256>>>(
        (const __half2*)p_h2h, dw_w, dw_b, (__half2*)p_h3h);
    // 7) fc2 GEMM + residual -> out
    gemm_h_kernel<false, true><<<dim3(C_ / BN, TOK_ / BM), 128, GSMEM>>>(
        p_h3h, p_wf2, fc2_b, p_x1, out, TOK_, C_, HID_);
}

// round 13
// speedup vs baseline: 1.0694x; 1.0163x over previous
#include <cuda_runtime.h>
#include <cuda_fp16.h>
#include <math.h>
#include <stdint.h>

// ---------------- problem constants ----------------
#define B_   8
#define HH_  56
#define WW_  56
#define N_   (HH_*WW_)          // 3136
#define C_   512
#define NH_  16
#define HD_  32
#define WS_  7
#define WS2_ 49
#define HID_ 2048
#define TOK_ (B_*N_)            // 25088
#define THREEC_ (3*C_)          // 1536

// ---------------- scratch ----------------
static __device__ __half g_hh  [(size_t)TOK_*C_];
static __device__ __half g_qkvh[(size_t)TOK_*THREEC_];
static __device__ float  g_x1  [(size_t)TOK_*C_];
static __device__ __half g_h2h [(size_t)TOK_*HID_];
static __device__ __half g_h3h [(size_t)TOK_*HID_];
static __device__ __half g_wq  [(size_t)THREEC_*C_];
static __device__ __half g_wf1 [(size_t)HID_*C_];
static __device__ __half g_wf2 [(size_t)C_*HID_];

// ---------------- fp32 -> fp16 conversion ----------------
__global__ __launch_bounds__(256)
void f2h_kernel(const float4* __restrict__ in, __half2* __restrict__ out, int n4) {
    int i = blockIdx.x * 256 + threadIdx.x;
    if (i >= n4) return;
    float4 v = in[i];
    out[2 * i]     = __floats2half2_rn(v.x, v.y);
    out[2 * i + 1] = __floats2half2_rn(v.z, v.w);
}

// ---------------- LayerNorm: warp per row ----------------
__global__ __launch_bounds__(256)
void ln_kernel(const float* __restrict__ x, const float* __restrict__ g,
               const float* __restrict__ b, __half* __restrict__ out) {
    __shared__ float sg[C_], sb[C_];
    const int tid = threadIdx.x;
    sg[tid] = g[tid]; sg[tid + 256] = g[tid + 256];
    sb[tid] = b[tid]; sb[tid + 256] = b[tid + 256];
    __syncthreads();

    const int lane = tid & 31, wid = tid >> 5;
    const long row = (long)blockIdx.x * 8 + wid;
    const float4* xr = (const float4*)(x + row * C_);

    float4 v[4];
    float sum = 0.0f;
    #pragma unroll
    for (int k = 0; k < 4; ++k) {
        v[k] = xr[lane + k * 32];
        sum += v[k].x + v[k].y + v[k].z + v[k].w;
    }
    #pragma unroll
    for (int o = 16; o > 0; o >>= 1) sum += __shfl_xor_sync(0xffffffffu, sum, o);
    float mu = sum * (1.0f / C_);

    float vs = 0.0f;
    #pragma unroll
    for (int k = 0; k < 4; ++k) {
        float dx = v[k].x - mu, dy = v[k].y - mu, dz = v[k].z - mu, dw = v[k].w - mu;
        vs += dx * dx + dy * dy + dz * dz + dw * dw;
    }
    #pragma unroll
    for (int o = 16; o > 0; o >>= 1) vs += __shfl_xor_sync(0xffffffffu, vs, o);
    float inv = rsqrtf(vs * (1.0f / C_) + 1e-5f);

    __half2* orow = (__half2*)(out + row * C_);
    #pragma unroll
    for (int k = 0; k < 4; ++k) {
        int i4 = lane + k * 32, c = i4 * 4;
        float e0 = (v[k].x - mu) * inv * sg[c]     + sb[c];
        float e1 = (v[k].y - mu) * inv * sg[c + 1] + sb[c + 1];
        float e2 = (v[k].z - mu) * inv * sg[c + 2] + sb[c + 2];
        float e3 = (v[k].w - mu) * inv * sg[c + 3] + sb[c + 3];
        orow[i4 * 2]     = __floats2half2_rn(e0, e1);
        orow[i4 * 2 + 1] = __floats2half2_rn(e2, e3);
    }
}

// ---------------- FP16 GEMM: 128x128 CTA, 4 warps 64x64, 3-stage (R6 exact) ---------
#define BM 128
#define BN 128
#define BKH 32
#define LST 40
#define STAGEH ((BM + BN) * LST)
#define GSMEM (3 * STAGEH * 2)

__device__ __forceinline__ void cpa16(uint32_t s, const void* g) {
    asm volatile("cp.async.ca.shared.global [%0], [%1], 16;" :: "r"(s), "l"(g));
}
__device__ __forceinline__ void ldsm4(uint32_t* r, uint32_t addr) {
    asm volatile("ldmatrix.sync.aligned.m8n8.x4.shared.b16 {%0,%1,%2,%3}, [%4];"
                 : "=r"(r[0]), "=r"(r[1]), "=r"(r[2]), "=r"(r[3]) : "r"(addr));
}
__device__ __forceinline__ void mma_f16(float* c, const uint32_t* a, const uint32_t* b) {
    asm volatile(
        "mma.sync.aligned.m16n8k16.row.col.f32.f16.f16.f32 "
        "{%0,%1,%2,%3}, {%4,%5,%6,%7}, {%8,%9}, {%0,%1,%2,%3};"
        : "+f"(c[0]), "+f"(c[1]), "+f"(c[2]), "+f"(c[3])
        : "r"(a[0]), "r"(a[1]), "r"(a[2]), "r"(a[3]), "r"(b[0]), "r"(b[1]));
}

template<bool OUT_HALF, bool HAS_RES>
__global__ __launch_bounds__(128, 2)
void gemm_h_kernel(const __half* __restrict__ A, const __half* __restrict__ Bm,
                   const float* __restrict__ bias, const float* __restrict__ res,
                   void* __restrict__ outv, int M, int N, int K) {
    extern __shared__ __half sm[];
    const uint32_t smb = (uint32_t)__cvta_generic_to_shared(sm);
    const int tid = threadIdx.x;
    const int lane = tid & 31, wid = tid >> 5;
    const int wm = wid & 1, wn = wid >> 1;
    const int g8 = lane >> 2, tig = lane & 3;
    const int m0 = blockIdx.y * BM, n0 = blockIdx.x * BN;

    float acc[4][8][4];
    #pragma unroll
    for (int i = 0; i < 4; ++i)
        #pragma unroll
        for (int j = 0; j < 8; ++j)
            #pragma unroll
            for (int t = 0; t < 4; ++t) acc[i][j][t] = 0.0f;

    const int T = K / BKH;
    const int lrow = tid >> 2, lq = tid & 3;

    auto load_stage = [&](int t, int s) {
        const int k0 = t * BKH;
        #pragma unroll
        for (int i = 0; i < 4; ++i) {
            int row = lrow + i * 32;
            uint32_t sa = smb + (uint32_t)(s * STAGEH + row * LST + lq * 8) * 2u;
            cpa16(sa, A + (long)(m0 + row) * K + k0 + lq * 8);
            cpa16(sa + BM * LST * 2u, Bm + (long)(n0 + row) * K + k0 + lq * 8);
        }
    };

    load_stage(0, 0);
    asm volatile("cp.async.commit_group;");
    if (T > 1) { load_stage(1, 1); asm volatile("cp.async.commit_group;"); }

    const int a_r = (lane & 15), a_k = (lane >> 4) * 8;
    const int b_r = (lane & 7), b_t = (lane >> 4), b_k = ((lane >> 3) & 1) * 8;

    for (int t = 0; t < T; ++t) {
        const int s = t % 3;
        if (t + 2 < T) {
            load_stage(t + 2, (t + 2) % 3);
            asm volatile("cp.async.commit_group;");
            asm volatile("cp.async.wait_group 2;");
        } else if (t + 1 < T) {
            asm volatile("cp.async.wait_group 1;");
        } else {
            asm volatile("cp.async.wait_group 0;");
        }
        __syncthreads();

        const uint32_t sA = smb + (uint32_t)(s * STAGEH) * 2u;
        const uint32_t sB = sA + BM * LST * 2u;

        #pragma unroll
        for (int kk = 0; kk < 2; ++kk) {
            const int kb = kk * 16;
            uint32_t a[4][4], b[8][2];
            #pragma unroll
            for (int i = 0; i < 4; ++i)
                ldsm4(a[i], sA + (uint32_t)((wm * 64 + i * 16 + a_r) * LST + kb + a_k) * 2u);
            #pragma unroll
            for (int jp = 0; jp < 4; ++jp) {
                uint32_t r[4];
                ldsm4(r, sB + (uint32_t)((wn * 64 + (jp * 2 + b_t) * 8 + b_r) * LST + kb + b_k) * 2u);
                b[jp * 2][0] = r[0]; b[jp * 2][1] = r[1];
                b[jp * 2 + 1][0] = r[2]; b[jp * 2 + 1][1] = r[3];
            }
            #pragma unroll
            for (int i = 0; i < 4; ++i)
                #pragma unroll
                for (int j = 0; j < 8; ++j) mma_f16(acc[i][j], a[i], b[j]);
        }
        __syncthreads();
    }

    // epilogue
    #pragma unroll
    for (int i = 0; i < 4; ++i) {
        int r = m0 + wm * 64 + i * 16 + g8;
        #pragma unroll
        for (int j = 0; j < 8; ++j) {
            int n = n0 + wn * 64 + j * 8 + tig * 2;
            float b0 = bias[n], b1 = bias[n + 1];
            float v0 = acc[i][j][0] + b0, v1 = acc[i][j][1] + b1;
            float v2 = acc[i][j][2] + b0, v3 = acc[i][j][3] + b1;
            long o0 = (long)r * N + n;
            long o1 = (long)(r + 8) * N + n;
            if (HAS_RES) {
                float2 r0 = *(const float2*)(res + o0);
                float2 r1 = *(const float2*)(res + o1);
                v0 += r0.x; v1 += r0.y; v2 += r1.x; v3 += r1.y;
            }
            if (OUT_HALF) {
                __half* out = (__half*)outv;
                *(__half2*)(out + o0) = __floats2half2_rn(v0, v1);
                *(__half2*)(out + o1) = __floats2half2_rn(v2, v3);
            } else {
                float* out = (float*)outv;
                *(float2*)(out + o0) = make_float2(v0, v1);
                *(float2*)(out + o1) = make_float2(v2, v3);
            }
        }
    }
}

// ---------------- Windowed attention (R6 proven version) ----------------------------
__global__ __launch_bounds__(256)
void attn_kernel(const __half* __restrict__ qkv, const float* __restrict__ rpb,
                 const float* __restrict__ x, float* __restrict__ x1) {
    const int head = blockIdx.x & 15;
    const int win  = blockIdx.x >> 4;
    const int b    = win >> 6;
    const int wi   = (win >> 3) & 7;
    const int wj   = win & 7;
    const int tid  = threadIdx.x;

    __shared__ float q[WS2_][HD_ + 1];
    __shared__ float k[WS2_][HD_ + 1];
    __shared__ float v[WS2_][HD_ + 1];
    __shared__ float s[WS2_][WS2_ + 1];

    for (int idx = tid; idx < WS2_ * 16; idx += 256) {
        int p = idx >> 4, d2 = idx & 15;
        int token = (wi * 7 + p / 7) * 56 + (wj * 7 + p % 7);
        long base = ((long)b * N_ + token) * THREEC_ + head * HD_ + 2 * d2;
        float2 fq = __half22float2(*(const __half2*)(qkv + base));
        float2 fk = __half22float2(*(const __half2*)(qkv + base + C_));
        float2 fv = __half22float2(*(const __half2*)(qkv + base + 2 * C_));
        q[p][2 * d2] = fq.x; q[p][2 * d2 + 1] = fq.y;
        k[p][2 * d2] = fk.x; k[p][2 * d2 + 1] = fk.y;
        v[p][2 * d2] = fv.x; v[p][2 * d2 + 1] = fv.y;
    }
    __syncthreads();

    const float scale = 0.17677669529663687f;
    for (int idx = tid; idx < WS2_ * WS2_; idx += 256) {
        int i = idx / WS2_, j = idx - i * WS2_;
        float acc = 0.0f;
        #pragma unroll
        for (int d = 0; d < HD_; ++d) acc = fmaf(q[i][d], k[j][d], acc);
        int dpi = (i / 7) - (j / 7) + 6;
        int dpj = (i % 7) - (j % 7) + 6;
        s[i][j] = acc * scale + rpb[(dpi * 13 + dpj) * NH_ + head];
    }
    __syncthreads();

    if (tid < WS2_) {
        float mx = -1e30f;
        #pragma unroll
        for (int j = 0; j < WS2_; ++j) mx = fmaxf(mx, s[tid][j]);
        float sum = 0.0f;
        #pragma unroll
        for (int j = 0; j < WS2_; ++j) { float e = __expf(s[tid][j] - mx); s[tid][j] = e; sum += e; }
        float inv = 1.0f / sum;
        #pragma unroll
        for (int j = 0; j < WS2_; ++j) s[tid][j] *= inv;
    }
    __syncthreads();

    for (int idx = tid; idx < WS2_ * HD_; idx += 256) {
        int i = idx >> 5, d = idx & 31;
        float acc = 0.0f;
        #pragma unroll
        for (int j = 0; j < WS2_; ++j) acc = fmaf(s[i][j], v[j][d], acc);
        int token = (wi * 7 + i / 7) * 56 + (wj * 7 + i % 7);
        long o = ((long)b * N_ + token) * C_ + head * HD_ + d;
        x1[o] = x[o] + acc;
    }
}

// ---------------- depthwise 3x3 + GELU: 4-row strip, sliding window ------------------
// grid = B_ * 14 strips * 4 chunks; block 256 threads = 256 channel-pairs.
// Each block outputs rows [r0, r0+4) x 56 cols; loads 6 rows once each (1.5x/output).
__global__ __launch_bounds__(256)
void dwconv_gelu_kernel(const __half2* __restrict__ h2, const float* __restrict__ w,
                        const float* __restrict__ bias, __half2* __restrict__ out) {
    __shared__ float ws[512 * 9];
    const int bid = blockIdx.x;
    const int chunk = bid & 3;
    const int strip = (bid >> 2) % 14;
    const int bb = (bid >> 2) / 14;
    const int r0 = strip * 4;
    const int cp = chunk * 256 + threadIdx.x;

    for (int q = threadIdx.x; q < 512 * 9; q += 256)
        ws[q] = w[(long)(chunk * 512) * 9 + q];
    __syncthreads();

    // hoist this thread's 18 weights into registers
    float wr[18];
    #pragma unroll
    for (int t = 0; t < 18; ++t) wr[t] = ws[(2 * threadIdx.x) * 9 + t];
    const int c = cp * 2;
    const float bi0 = bias[c], bi1 = bias[c + 1];

    // 6 row bases (abs rows r0-1 .. r0+4); flag invalid rows
    long rb[6];
    bool rv[6];
    #pragma unroll
    for (int j = 0; j < 6; ++j) {
        int r = r0 - 1 + j;
        rv[j] = (r >= 0 && r < 56);
        rb[j] = (((long)bb * 56 + (rv[j] ? r : 0)) * 56) * 1024 + cp;
    }

    // sliding columns: col[dx][rowj], dx: 0=w-1, 1=w, 2=w+1
    float2 col[3][6];
    #pragma unroll
    for (int j = 0; j < 6; ++j) {
        col[0][j] = make_float2(0.f, 0.f);
        col[1][j] = rv[j] ? __half22float2(h2[rb[j]]) : make_float2(0.f, 0.f);
    }

    for (int wcol = 0; wcol < 56; ++wcol) {
        if (wcol + 1 < 56) {
            long o = (long)(wcol + 1) * 1024;
            #pragma unroll
            for (int j = 0; j < 6; ++j)
                col[2][j] = rv[j] ? __half22float2(h2[rb[j] + o]) : make_float2(0.f, 0.f);
        } else {
            #pragma unroll
            for (int j = 0; j < 6; ++j) col[2][j] = make_float2(0.f, 0.f);
        }

        #pragma unroll
        for (int rr = 0; rr < 4; ++rr) {
            float a0 = bi0, a1 = bi1;
            #pragma unroll
            for (int dy = 0; dy < 3; ++dy) {
                #pragma unroll
                for (int dx = 0; dx < 3; ++dx) {
                    float2 vv = col[dx][rr + dy];
                    a0 = fmaf(vv.x, wr[dy * 3 + dx], a0);
                    a1 = fmaf(vv.y, wr[9 + dy * 3 + dx], a1);
                }
            }
            float g0 = 0.5f * a0 * (1.0f + erff(a0 * 0.70710678118654752f));
            float g1 = 0.5f * a1 * (1.0f + erff(a1 * 0.70710678118654752f));
            out[(((long)bb * 56 + (r0 + rr)) * 56 + wcol) * 1024 + cp] = __floats2half2_rn(g0, g1);
        }

        #pragma unroll
        for (int j = 0; j < 6; ++j) { col[0][j] = col[1][j]; col[1][j] = col[2][j]; }
    }
}

// ---------------- launch ----------------
extern "C" void kernel_launch(void* const* d_in, const int* in_sizes, int n_in,
                              void* d_out, int out_size) {
    const float* x       = (const float*)d_in[0];
    const float* norm1_g = (const float*)d_in[3];
    const float* norm1_b = (const float*)d_in[4];
    const float* norm2_g = (const float*)d_in[5];
    const float* norm2_b = (const float*)d_in[6];
    const float* qkv_w   = (const float*)d_in[7];
    const float* qkv_b   = (const float*)d_in[8];
    const float* rpb     = (const float*)d_in[9];
    const float* fc1_w   = (const float*)d_in[10];
    const float* fc1_b   = (const float*)d_in[11];
    const float* dw_w    = (const float*)d_in[12];
    const float* dw_b    = (const float*)d_in[13];
    const float* fc2_w   = (const float*)d_in[14];
    const float* fc2_b   = (const float*)d_in[15];
    float* out = (float*)d_out;

    __half *p_hh, *p_qkvh, *p_h2h, *p_h3h, *p_wq, *p_wf1, *p_wf2;
    float *p_x1;
    cudaGetSymbolAddress((void**)&p_hh,   g_hh);
    cudaGetSymbolAddress((void**)&p_qkvh, g_qkvh);
    cudaGetSymbolAddress((void**)&p_x1,   g_x1);
    cudaGetSymbolAddress((void**)&p_h2h,  g_h2h);
    cudaGetSymbolAddress((void**)&p_h3h,  g_h3h);
    cudaGetSymbolAddress((void**)&p_wq,   g_wq);
    cudaGetSymbolAddress((void**)&p_wf1,  g_wf1);
    cudaGetSymbolAddress((void**)&p_wf2,  g_wf2);

    cudaFuncSetAttribute(gemm_h_kernel<true, false>,
                         cudaFuncAttributeMaxDynamicSharedMemorySize, GSMEM);
    cudaFuncSetAttribute(gemm_h_kernel<false, true>,
                         cudaFuncAttributeMaxDynamicSharedMemorySize, GSMEM);

    // 0) weight conversions
    f2h_kernel<<<(THREEC_ * C_ / 4 + 255) / 256, 256>>>((const float4*)qkv_w, (__half2*)p_wq, THREEC_ * C_ / 4);
    f2h_kernel<<<(HID_ * C_ / 4 + 255) / 256, 256>>>((const float4*)fc1_w, (__half2*)p_wf1, HID_ * C_ / 4);
    f2h_kernel<<<(C_ * HID_ / 4 + 255) / 256, 256>>>((const float4*)fc2_w, (__half2*)p_wf2, C_ * HID_ / 4);

    // 1) LN1
    ln_kernel<<<TOK_ / 8, 256>>>(x, norm1_g, norm1_b, p_hh);
    // 2) QKV GEMM
    gemm_h_kernel<true, false><<<dim3(THREEC_ / BN, TOK_ / BM), 128, GSMEM>>>(
        p_hh, p_wq, qkv_b, nullptr, p_qkvh, TOK_, THREEC_, C_);
    // 3) windowed attention + residual
    attn_kernel<<<B_ * 64 * NH_, 256>>>(p_qkvh, rpb, x, p_x1);
    // 4) LN2
    ln_kernel<<<TOK_ / 8, 256>>>(p_x1, norm2_g, norm2_b, p_hh);
    // 5) fc1 GEMM
    gemm_h_kernel<true, false><<<dim3(HID_ / BN, TOK_ / BM), 128, GSMEM>>>(
        p_hh, p_wf1, fc1_b, nullptr, p_h2h, TOK_, HID_, C_);
    // 6) depthwise conv + GELU (4-row strips)
    dwconv_gelu_kernel<<<B_ * 14 * 4, 256>>>(
        (const __half2*)p_h2h, dw_w, dw_b, (__half2*)p_h3h);
    // 7) fc2 GEMM + residual -> out
    gemm_h_kernel<false, true><<<dim3(C_ / BN, TOK_ / BM), 128, GSMEM>>>(
        p_h3h, p_wf2, fc2_b, p_x1, out, TOK_, C_, HID_);
}

// round 14
// speedup vs baseline: 1.0726x; 1.0030x over previous
#include <cuda_runtime.h>
#include <cuda_fp16.h>
#include <math.h>
#include <stdint.h>

// ---------------- problem constants ----------------
#define B_   8
#define HH_  56
#define WW_  56
#define N_   (HH_*WW_)          // 3136
#define C_   512
#define NH_  16
#define HD_  32
#define WS_  7
#define WS2_ 49
#define HID_ 2048
#define TOK_ (B_*N_)            // 25088
#define THREEC_ (3*C_)          // 1536

// ---------------- scratch ----------------
static __device__ __half g_hh  [(size_t)TOK_*C_];
static __device__ __half g_qkvh[(size_t)TOK_*THREEC_];
static __device__ float  g_x1  [(size_t)TOK_*C_];
static __device__ __half g_h2h [(size_t)TOK_*HID_];
static __device__ __half g_h3h [(size_t)TOK_*HID_];
static __device__ __half g_wq  [(size_t)THREEC_*C_];
static __device__ __half g_wf1 [(size_t)HID_*C_];
static __device__ __half g_wf2 [(size_t)C_*HID_];

// ---------------- fused fp32 -> fp16 conversion for all 3 weight tensors ------------
#define F2H_N1 (THREEC_ * C_ / 4 / 256)    // 768 blocks for qkv_w
#define F2H_N2 (HID_ * C_ / 4 / 256)       // 1024 blocks for fc1_w
#define F2H_N3 (C_ * HID_ / 4 / 256)       // 1024 blocks for fc2_w
__global__ __launch_bounds__(256)
void f2h_all_kernel(const float4* __restrict__ w0, const float4* __restrict__ w1,
                    const float4* __restrict__ w2, __half2* __restrict__ o0,
                    __half2* __restrict__ o1, __half2* __restrict__ o2) {
    int bid = blockIdx.x;
    const float4* in;
    __half2* out;
    int base;
    if (bid < F2H_N1) { in = w0; out = o0; base = bid; }
    else if (bid < F2H_N1 + F2H_N2) { in = w1; out = o1; base = bid - F2H_N1; }
    else { in = w2; out = o2; base = bid - F2H_N1 - F2H_N2; }
    int i = base * 256 + threadIdx.x;
    float4 v = in[i];
    out[2 * i]     = __floats2half2_rn(v.x, v.y);
    out[2 * i + 1] = __floats2half2_rn(v.z, v.w);
}

// ---------------- LayerNorm: warp per row ----------------
__global__ __launch_bounds__(256)
void ln_kernel(const float* __restrict__ x, const float* __restrict__ g,
               const float* __restrict__ b, __half* __restrict__ out) {
    __shared__ float sg[C_], sb[C_];
    const int tid = threadIdx.x;
    sg[tid] = g[tid]; sg[tid + 256] = g[tid + 256];
    sb[tid] = b[tid]; sb[tid + 256] = b[tid + 256];
    __syncthreads();

    const int lane = tid & 31, wid = tid >> 5;
    const long row = (long)blockIdx.x * 8 + wid;
    const float4* xr = (const float4*)(x + row * C_);

    float4 v[4];
    float sum = 0.0f;
    #pragma unroll
    for (int k = 0; k < 4; ++k) {
        v[k] = xr[lane + k * 32];
        sum += v[k].x + v[k].y + v[k].z + v[k].w;
    }
    #pragma unroll
    for (int o = 16; o > 0; o >>= 1) sum += __shfl_xor_sync(0xffffffffu, sum, o);
    float mu = sum * (1.0f / C_);

    float vs = 0.0f;
    #pragma unroll
    for (int k = 0; k < 4; ++k) {
        float dx = v[k].x - mu, dy = v[k].y - mu, dz = v[k].z - mu, dw = v[k].w - mu;
        vs += dx * dx + dy * dy + dz * dz + dw * dw;
    }
    #pragma unroll
    for (int o = 16; o > 0; o >>= 1) vs += __shfl_xor_sync(0xffffffffu, vs, o);
    float inv = rsqrtf(vs * (1.0f / C_) + 1e-5f);

    __half2* orow = (__half2*)(out + row * C_);
    #pragma unroll
    for (int k = 0; k < 4; ++k) {
        int i4 = lane + k * 32, c = i4 * 4;
        float e0 = (v[k].x - mu) * inv * sg[c]     + sb[c];
        float e1 = (v[k].y - mu) * inv * sg[c + 1] + sb[c + 1];
        float e2 = (v[k].z - mu) * inv * sg[c + 2] + sb[c + 2];
        float e3 = (v[k].w - mu) * inv * sg[c + 3] + sb[c + 3];
        orow[i4 * 2]     = __floats2half2_rn(e0, e1);
        orow[i4 * 2 + 1] = __floats2half2_rn(e2, e3);
    }
}

// ---------------- FP16 GEMM: 128x128 CTA, 4 warps 64x64, 3-stage (R6 exact) ---------
#define BM 128
#define BN 128
#define BKH 32
#define LST 40
#define STAGEH ((BM + BN) * LST)
#define GSMEM (3 * STAGEH * 2)

__device__ __forceinline__ void cpa16(uint32_t s, const void* g) {
    asm volatile("cp.async.ca.shared.global [%0], [%1], 16;" :: "r"(s), "l"(g));
}
__device__ __forceinline__ void ldsm4(uint32_t* r, uint32_t addr) {
    asm volatile("ldmatrix.sync.aligned.m8n8.x4.shared.b16 {%0,%1,%2,%3}, [%4];"
                 : "=r"(r[0]), "=r"(r[1]), "=r"(r[2]), "=r"(r[3]) : "r"(addr));
}
__device__ __forceinline__ void mma_f16(float* c, const uint32_t* a, const uint32_t* b) {
    asm volatile(
        "mma.sync.aligned.m16n8k16.row.col.f32.f16.f16.f32 "
        "{%0,%1,%2,%3}, {%4,%5,%6,%7}, {%8,%9}, {%0,%1,%2,%3};"
        : "+f"(c[0]), "+f"(c[1]), "+f"(c[2]), "+f"(c[3])
        : "r"(a[0]), "r"(a[1]), "r"(a[2]), "r"(a[3]), "r"(b[0]), "r"(b[1]));
}

template<bool OUT_HALF, bool HAS_RES>
__global__ __launch_bounds__(128, 2)
void gemm_h_kernel(const __half* __restrict__ A, const __half* __restrict__ Bm,
                   const float* __restrict__ bias, const float* __restrict__ res,
                   void* __restrict__ outv, int M, int N, int K) {
    extern __shared__ __half sm[];
    const uint32_t smb = (uint32_t)__cvta_generic_to_shared(sm);
    const int tid = threadIdx.x;
    const int lane = tid & 31, wid = tid >> 5;
    const int wm = wid & 1, wn = wid >> 1;
    const int g8 = lane >> 2, tig = lane & 3;
    const int m0 = blockIdx.y * BM, n0 = blockIdx.x * BN;

    float acc[4][8][4];
    #pragma unroll
    for (int i = 0; i < 4; ++i)
        #pragma unroll
        for (int j = 0; j < 8; ++j)
            #pragma unroll
            for (int t = 0; t < 4; ++t) acc[i][j][t] = 0.0f;

    const int T = K / BKH;
    const int lrow = tid >> 2, lq = tid & 3;

    auto load_stage = [&](int t, int s) {
        const int k0 = t * BKH;
        #pragma unroll
        for (int i = 0; i < 4; ++i) {
            int row = lrow + i * 32;
            uint32_t sa = smb + (uint32_t)(s * STAGEH + row * LST + lq * 8) * 2u;
            cpa16(sa, A + (long)(m0 + row) * K + k0 + lq * 8);
            cpa16(sa + BM * LST * 2u, Bm + (long)(n0 + row) * K + k0 + lq * 8);
        }
    };

    load_stage(0, 0);
    asm volatile("cp.async.commit_group;");
    if (T > 1) { load_stage(1, 1); asm volatile("cp.async.commit_group;"); }

    const int a_r = (lane & 15), a_k = (lane >> 4) * 8;
    const int b_r = (lane & 7), b_t = (lane >> 4), b_k = ((lane >> 3) & 1) * 8;

    for (int t = 0; t < T; ++t) {
        const int s = t % 3;
        if (t + 2 < T) {
            load_stage(t + 2, (t + 2) % 3);
            asm volatile("cp.async.commit_group;");
            asm volatile("cp.async.wait_group 2;");
        } else if (t + 1 < T) {
            asm volatile("cp.async.wait_group 1;");
        } else {
            asm volatile("cp.async.wait_group 0;");
        }
        __syncthreads();

        const uint32_t sA = smb + (uint32_t)(s * STAGEH) * 2u;
        const uint32_t sB = sA + BM * LST * 2u;

        #pragma unroll
        for (int kk = 0; kk < 2; ++kk) {
            const int kb = kk * 16;
            uint32_t a[4][4], b[8][2];
            #pragma unroll
            for (int i = 0; i < 4; ++i)
                ldsm4(a[i], sA + (uint32_t)((wm * 64 + i * 16 + a_r) * LST + kb + a_k) * 2u);
            #pragma unroll
            for (int jp = 0; jp < 4; ++jp) {
                uint32_t r[4];
                ldsm4(r, sB + (uint32_t)((wn * 64 + (jp * 2 + b_t) * 8 + b_r) * LST + kb + b_k) * 2u);
                b[jp * 2][0] = r[0]; b[jp * 2][1] = r[1];
                b[jp * 2 + 1][0] = r[2]; b[jp * 2 + 1][1] = r[3];
            }
            #pragma unroll
            for (int i = 0; i < 4; ++i)
                #pragma unroll
                for (int j = 0; j < 8; ++j) mma_f16(acc[i][j], a[i], b[j]);
        }
        __syncthreads();
    }

    // epilogue
    #pragma unroll
    for (int i = 0; i < 4; ++i) {
        int r = m0 + wm * 64 + i * 16 + g8;
        #pragma unroll
        for (int j = 0; j < 8; ++j) {
            int n = n0 + wn * 64 + j * 8 + tig * 2;
            float b0 = bias[n], b1 = bias[n + 1];
            float v0 = acc[i][j][0] + b0, v1 = acc[i][j][1] + b1;
            float v2 = acc[i][j][2] + b0, v3 = acc[i][j][3] + b1;
            long o0 = (long)r * N + n;
            long o1 = (long)(r + 8) * N + n;
            if (HAS_RES) {
                float2 r0 = *(const float2*)(res + o0);
                float2 r1 = *(const float2*)(res + o1);
                v0 += r0.x; v1 += r0.y; v2 += r1.x; v3 += r1.y;
            }
            if (OUT_HALF) {
                __half* out = (__half*)outv;
                *(__half2*)(out + o0) = __floats2half2_rn(v0, v1);
                *(__half2*)(out + o1) = __floats2half2_rn(v2, v3);
            } else {
                float* out = (float*)outv;
                *(float2*)(out + o0) = make_float2(v0, v1);
                *(float2*)(out + o1) = make_float2(v2, v3);
            }
        }
    }
}

// ---------------- Windowed attention (R6 proven version) ----------------------------
__global__ __launch_bounds__(256)
void attn_kernel(const __half* __restrict__ qkv, const float* __restrict__ rpb,
                 const float* __restrict__ x, float* __restrict__ x1) {
    const int head = blockIdx.x & 15;
    const int win  = blockIdx.x >> 4;
    const int b    = win >> 6;
    const int wi   = (win >> 3) & 7;
    const int wj   = win & 7;
    const int tid  = threadIdx.x;

    __shared__ float q[WS2_][HD_ + 1];
    __shared__ float k[WS2_][HD_ + 1];
    __shared__ float v[WS2_][HD_ + 1];
    __shared__ float s[WS2_][WS2_ + 1];

    for (int idx = tid; idx < WS2_ * 16; idx += 256) {
        int p = idx >> 4, d2 = idx & 15;
        int token = (wi * 7 + p / 7) * 56 + (wj * 7 + p % 7);
        long base = ((long)b * N_ + token) * THREEC_ + head * HD_ + 2 * d2;
        float2 fq = __half22float2(*(const __half2*)(qkv + base));
        float2 fk = __half22float2(*(const __half2*)(qkv + base + C_));
        float2 fv = __half22float2(*(const __half2*)(qkv + base + 2 * C_));
        q[p][2 * d2] = fq.x; q[p][2 * d2 + 1] = fq.y;
        k[p][2 * d2] = fk.x; k[p][2 * d2 + 1] = fk.y;
        v[p][2 * d2] = fv.x; v[p][2 * d2 + 1] = fv.y;
    }
    __syncthreads();

    const float scale = 0.17677669529663687f;
    for (int idx = tid; idx < WS2_ * WS2_; idx += 256) {
        int i = idx / WS2_, j = idx - i * WS2_;
        float acc = 0.0f;
        #pragma unroll
        for (int d = 0; d < HD_; ++d) acc = fmaf(q[i][d], k[j][d], acc);
        int dpi = (i / 7) - (j / 7) + 6;
        int dpj = (i % 7) - (j % 7) + 6;
        s[i][j] = acc * scale + rpb[(dpi * 13 + dpj) * NH_ + head];
    }
    __syncthreads();

    if (tid < WS2_) {
        float mx = -1e30f;
        #pragma unroll
        for (int j = 0; j < WS2_; ++j) mx = fmaxf(mx, s[tid][j]);
        float sum = 0.0f;
        #pragma unroll
        for (int j = 0; j < WS2_; ++j) { float e = __expf(s[tid][j] - mx); s[tid][j] = e; sum += e; }
        float inv = 1.0f / sum;
        #pragma unroll
        for (int j = 0; j < WS2_; ++j) s[tid][j] *= inv;
    }
    __syncthreads();

    for (int idx = tid; idx < WS2_ * HD_; idx += 256) {
        int i = idx >> 5, d = idx & 31;
        float acc = 0.0f;
        #pragma unroll
        for (int j = 0; j < WS2_; ++j) acc = fmaf(s[i][j], v[j][d], acc);
        int token = (wi * 7 + i / 7) * 56 + (wj * 7 + i % 7);
        long o = ((long)b * N_ + token) * C_ + head * HD_ + d;
        x1[o] = x[o] + acc;
    }
}

// ---------------- depthwise 3x3 + GELU: 8-row strip, sliding window ------------------
// grid = B_ * 7 strips * 4 chunks = 224 blocks; block 256 threads = 256 channel-pairs.
__global__ __launch_bounds__(256)
void dwconv_gelu_kernel(const __half2* __restrict__ h2, const float* __restrict__ w,
                        const float* __restrict__ bias, __half2* __restrict__ out) {
    __shared__ float ws[512 * 9];
    const int bid = blockIdx.x;
    const int chunk = bid & 3;
    const int strip = (bid >> 2) % 7;
    const int bb = (bid >> 2) / 7;
    const int r0 = strip * 8;
    const int cp = chunk * 256 + threadIdx.x;

    for (int q = threadIdx.x; q < 512 * 9; q += 256)
        ws[q] = w[(long)(chunk * 512) * 9 + q];
    __syncthreads();

    float wr[18];
    #pragma unroll
    for (int t = 0; t < 18; ++t) wr[t] = ws[(2 * threadIdx.x) * 9 + t];
    const int c = cp * 2;
    const float bi0 = bias[c], bi1 = bias[c + 1];

    // 10 row bases (abs rows r0-1 .. r0+8); flag invalid rows
    long rb[10];
    bool rv[10];
    #pragma unroll
    for (int j = 0; j < 10; ++j) {
        int r = r0 - 1 + j;
        rv[j] = (r >= 0 && r < 56);
        rb[j] = (((long)bb * 56 + (rv[j] ? r : 0)) * 56) * 1024 + cp;
    }

    float2 col[3][10];
    #pragma unroll
    for (int j = 0; j < 10; ++j) {
        col[0][j] = make_float2(0.f, 0.f);
        col[1][j] = rv[j] ? __half22float2(h2[rb[j]]) : make_float2(0.f, 0.f);
    }

    for (int wcol = 0; wcol < 56; ++wcol) {
        if (wcol + 1 < 56) {
            long o = (long)(wcol + 1) * 1024;
            #pragma unroll
            for (int j = 0; j < 10; ++j)
                col[2][j] = rv[j] ? __half22float2(h2[rb[j] + o]) : make_float2(0.f, 0.f);
        } else {
            #pragma unroll
            for (int j = 0; j < 10; ++j) col[2][j] = make_float2(0.f, 0.f);
        }

        #pragma unroll
        for (int rr = 0; rr < 8; ++rr) {
            float a0 = bi0, a1 = bi1;
            #pragma unroll
            for (int dy = 0; dy < 3; ++dy) {
                #pragma unroll
                for (int dx = 0; dx < 3; ++dx) {
                    float2 vv = col[dx][rr + dy];
                    a0 = fmaf(vv.x, wr[dy * 3 + dx], a0);
                    a1 = fmaf(vv.y, wr[9 + dy * 3 + dx], a1);
                }
            }
            float g0 = 0.5f * a0 * (1.0f + erff(a0 * 0.70710678118654752f));
            float g1 = 0.5f * a1 * (1.0f + erff(a1 * 0.70710678118654752f));
            out[(((long)bb * 56 + (r0 + rr)) * 56 + wcol) * 1024 + cp] = __floats2half2_rn(g0, g1);
        }

        #pragma unroll
        for (int j = 0; j < 10; ++j) { col[0][j] = col[1][j]; col[1][j] = col[2][j]; }
    }
}

// ---------------- launch ----------------
extern "C" void kernel_launch(void* const* d_in, const int* in_sizes, int n_in,
                              void* d_out, int out_size) {
    const float* x       = (const float*)d_in[0];
    const float* norm1_g = (const float*)d_in[3];
    const float* norm1_b = (const float*)d_in[4];
    const float* norm2_g = (const float*)d_in[5];
    const float* norm2_b = (const float*)d_in[6];
    const float* qkv_w   = (const float*)d_in[7];
    const float* qkv_b   = (const float*)d_in[8];
    const float* rpb     = (const float*)d_in[9];
    const float* fc1_w   = (const float*)d_in[10];
    const float* fc1_b   = (const float*)d_in[11];
    const float* dw_w    = (const float*)d_in[12];
    const float* dw_b    = (const float*)d_in[13];
    const float* fc2_w   = (const float*)d_in[14];
    const float* fc2_b   = (const float*)d_in[15];
    float* out = (float*)d_out;

    __half *p_hh, *p_qkvh, *p_h2h, *p_h3h, *p_wq, *p_wf1, *p_wf2;
    float *p_x1;
    cudaGetSymbolAddress((void**)&p_hh,   g_hh);
    cudaGetSymbolAddress((void**)&p_qkvh, g_qkvh);
    cudaGetSymbolAddress((void**)&p_x1,   g_x1);
    cudaGetSymbolAddress((void**)&p_h2h,  g_h2h);
    cudaGetSymbolAddress((void**)&p_h3h,  g_h3h);
    cudaGetSymbolAddress((void**)&p_wq,   g_wq);
    cudaGetSymbolAddress((void**)&p_wf1,  g_wf1);
    cudaGetSymbolAddress((void**)&p_wf2,  g_wf2);

    cudaFuncSetAttribute(gemm_h_kernel<true, false>,
                         cudaFuncAttributeMaxDynamicSharedMemorySize, GSMEM);
    cudaFuncSetAttribute(gemm_h_kernel<false, true>,
                         cudaFuncAttributeMaxDynamicSharedMemorySize, GSMEM);

    // 0) weight conversions (one fused launch)
    f2h_all_kernel<<<F2H_N1 + F2H_N2 + F2H_N3, 256>>>(
        (const float4*)qkv_w, (const float4*)fc1_w, (const float4*)fc2_w,
        (__half2*)p_wq, (__half2*)p_wf1, (__half2*)p_wf2);

    // 1) LN1
    ln_kernel<<<TOK_ / 8, 256>>>(x, norm1_g, norm1_b, p_hh);
    // 2) QKV GEMM
    gemm_h_kernel<true, false><<<dim3(THREEC_ / BN, TOK_ / BM), 128, GSMEM>>>(
        p_hh, p_wq, qkv_b, nullptr, p_qkvh, TOK_, THREEC_, C_);
    // 3) windowed attention + residual
    attn_kernel<<<B_ * 64 * NH_, 256>>>(p_qkvh, rpb, x, p_x1);
    // 4) LN2
    ln_kernel<<<TOK_ / 8, 256>>>(p_x1, norm2_g, norm2_b, p_hh);
    // 5) fc1 GEMM
    gemm_h_kernel<true, false><<<dim3(HID_ / BN, TOK_ / BM), 128, GSMEM>>>(
        p_hh, p_wf1, fc1_b, nullptr, p_h2h, TOK_, HID_, C_);
    // 6) depthwise conv + GELU (8-row strips)
    dwconv_gelu_kernel<<<B_ * 7 * 4, 256>>>(
        (const __half2*)p_h2h, dw_w, dw_b, (__half2*)p_h3h);
    // 7) fc2 GEMM + residual -> out
    gemm_h_kernel<false, true><<<dim3(C_ / BN, TOK_ / BM), 128, GSMEM>>>(
        p_h3h, p_wf2, fc2_b, p_x1, out, TOK_, C_, HID_);
}

// round 15
// speedup vs baseline: 1.3866x; 1.2928x over previous
#include <cuda_runtime.h>
#include <cuda_fp16.h>
#include <math.h>
#include <stdint.h>

// ---------------- problem constants ----------------
#define B_   8
#define HH_  56
#define WW_  56
#define N_   (HH_*WW_)          // 3136
#define C_   512
#define NH_  16
#define HD_  32
#define WS_  7
#define WS2_ 49
#define HID_ 2048
#define TOK_ (B_*N_)            // 25088
#define THREEC_ (3*C_)          // 1536

// ---------------- scratch ----------------
static __device__ __half g_hh  [(size_t)TOK_*C_];
static __device__ __half g_qkvh[(size_t)TOK_*THREEC_];
static __device__ float  g_x1  [(size_t)TOK_*C_];
static __device__ __half g_h2h [(size_t)TOK_*HID_];
static __device__ __half g_h3h [(size_t)TOK_*HID_];
static __device__ __half g_wq  [(size_t)THREEC_*C_];
static __device__ __half g_wf1 [(size_t)HID_*C_];
static __device__ __half g_wf2 [(size_t)C_*HID_];

// ---------------- fused fp32 -> fp16 conversion ----------------
#define F2H_N1 (THREEC_ * C_ / 4 / 256)
#define F2H_N2 (HID_ * C_ / 4 / 256)
#define F2H_N3 (C_ * HID_ / 4 / 256)
__global__ __launch_bounds__(256)
void f2h_all_kernel(const float4* __restrict__ w0, const float4* __restrict__ w1,
                    const float4* __restrict__ w2, __half2* __restrict__ o0,
                    __half2* __restrict__ o1, __half2* __restrict__ o2) {
    int bid = blockIdx.x;
    const float4* in;
    __half2* out;
    int base;
    if (bid < F2H_N1) { in = w0; out = o0; base = bid; }
    else if (bid < F2H_N1 + F2H_N2) { in = w1; out = o1; base = bid - F2H_N1; }
    else { in = w2; out = o2; base = bid - F2H_N1 - F2H_N2; }
    int i = base * 256 + threadIdx.x;
    float4 v = in[i];
    out[2 * i]     = __floats2half2_rn(v.x, v.y);
    out[2 * i + 1] = __floats2half2_rn(v.z, v.w);
}

// ---------------- LayerNorm: warp per row ----------------
__global__ __launch_bounds__(256)
void ln_kernel(const float* __restrict__ x, const float* __restrict__ g,
               const float* __restrict__ b, __half* __restrict__ out) {
    __shared__ float sg[C_], sb[C_];
    const int tid = threadIdx.x;
    sg[tid] = g[tid]; sg[tid + 256] = g[tid + 256];
    sb[tid] = b[tid]; sb[tid + 256] = b[tid + 256];
    __syncthreads();

    const int lane = tid & 31, wid = tid >> 5;
    const long row = (long)blockIdx.x * 8 + wid;
    const float4* xr = (const float4*)(x + row * C_);

    float4 v[4];
    float sum = 0.0f;
    #pragma unroll
    for (int k = 0; k < 4; ++k) {
        v[k] = xr[lane + k * 32];
        sum += v[k].x + v[k].y + v[k].z + v[k].w;
    }
    #pragma unroll
    for (int o = 16; o > 0; o >>= 1) sum += __shfl_xor_sync(0xffffffffu, sum, o);
    float mu = sum * (1.0f / C_);

    float vs = 0.0f;
    #pragma unroll
    for (int k = 0; k < 4; ++k) {
        float dx = v[k].x - mu, dy = v[k].y - mu, dz = v[k].z - mu, dw = v[k].w - mu;
        vs += dx * dx + dy * dy + dz * dz + dw * dw;
    }
    #pragma unroll
    for (int o = 16; o > 0; o >>= 1) vs += __shfl_xor_sync(0xffffffffu, vs, o);
    float inv = rsqrtf(vs * (1.0f / C_) + 1e-5f);

    __half2* orow = (__half2*)(out + row * C_);
    #pragma unroll
    for (int k = 0; k < 4; ++k) {
        int i4 = lane + k * 32, c = i4 * 4;
        float e0 = (v[k].x - mu) * inv * sg[c]     + sb[c];
        float e1 = (v[k].y - mu) * inv * sg[c + 1] + sb[c + 1];
        float e2 = (v[k].z - mu) * inv * sg[c + 2] + sb[c + 2];
        float e3 = (v[k].w - mu) * inv * sg[c + 3] + sb[c + 3];
        orow[i4 * 2]     = __floats2half2_rn(e0, e1);
        orow[i4 * 2 + 1] = __floats2half2_rn(e2, e3);
    }
}

// ---------------- shared PTX primitives ----------------
__device__ __forceinline__ void cpa16(uint32_t s, const void* g) {
    asm volatile("cp.async.ca.shared.global [%0], [%1], 16;" :: "r"(s), "l"(g));
}
__device__ __forceinline__ void ldsm4(uint32_t* r, uint32_t addr) {
    asm volatile("ldmatrix.sync.aligned.m8n8.x4.shared.b16 {%0,%1,%2,%3}, [%4];"
                 : "=r"(r[0]), "=r"(r[1]), "=r"(r[2]), "=r"(r[3]) : "r"(addr));
}
__device__ __forceinline__ void ldsm4t(uint32_t* r, uint32_t addr) {
    asm volatile("ldmatrix.sync.aligned.m8n8.x4.trans.shared.b16 {%0,%1,%2,%3}, [%4];"
                 : "=r"(r[0]), "=r"(r[1]), "=r"(r[2]), "=r"(r[3]) : "r"(addr));
}
__device__ __forceinline__ void mma_f16(float* c, const uint32_t* a, const uint32_t* b) {
    asm volatile(
        "mma.sync.aligned.m16n8k16.row.col.f32.f16.f16.f32 "
        "{%0,%1,%2,%3}, {%4,%5,%6,%7}, {%8,%9}, {%0,%1,%2,%3};"
        : "+f"(c[0]), "+f"(c[1]), "+f"(c[2]), "+f"(c[3])
        : "r"(a[0]), "r"(a[1]), "r"(a[2]), "r"(a[3]), "r"(b[0]), "r"(b[1]));
}

// ---------------- FP16 GEMM: 128x128 CTA, 4 warps 64x64, 3-stage (R6 exact) ---------
#define BM 128
#define BN 128
#define BKH 32
#define LST 40
#define STAGEH ((BM + BN) * LST)
#define GSMEM (3 * STAGEH * 2)

template<bool OUT_HALF, bool HAS_RES>
__global__ __launch_bounds__(128, 2)
void gemm_h_kernel(const __half* __restrict__ A, const __half* __restrict__ Bm,
                   const float* __restrict__ bias, const float* __restrict__ res,
                   void* __restrict__ outv, int M, int N, int K) {
    extern __shared__ __half sm[];
    const uint32_t smb = (uint32_t)__cvta_generic_to_shared(sm);
    const int tid = threadIdx.x;
    const int lane = tid & 31, wid = tid >> 5;
    const int wm = wid & 1, wn = wid >> 1;
    const int g8 = lane >> 2, tig = lane & 3;
    const int m0 = blockIdx.y * BM, n0 = blockIdx.x * BN;

    float acc[4][8][4];
    #pragma unroll
    for (int i = 0; i < 4; ++i)
        #pragma unroll
        for (int j = 0; j < 8; ++j)
            #pragma unroll
            for (int t = 0; t < 4; ++t) acc[i][j][t] = 0.0f;

    const int T = K / BKH;
    const int lrow = tid >> 2, lq = tid & 3;

    auto load_stage = [&](int t, int s) {
        const int k0 = t * BKH;
        #pragma unroll
        for (int i = 0; i < 4; ++i) {
            int row = lrow + i * 32;
            uint32_t sa = smb + (uint32_t)(s * STAGEH + row * LST + lq * 8) * 2u;
            cpa16(sa, A + (long)(m0 + row) * K + k0 + lq * 8);
            cpa16(sa + BM * LST * 2u, Bm + (long)(n0 + row) * K + k0 + lq * 8);
        }
    };

    load_stage(0, 0);
    asm volatile("cp.async.commit_group;");
    if (T > 1) { load_stage(1, 1); asm volatile("cp.async.commit_group;"); }

    const int a_r = (lane & 15), a_k = (lane >> 4) * 8;
    const int b_r = (lane & 7), b_t = (lane >> 4), b_k = ((lane >> 3) & 1) * 8;

    for (int t = 0; t < T; ++t) {
        const int s = t % 3;
        if (t + 2 < T) {
            load_stage(t + 2, (t + 2) % 3);
            asm volatile("cp.async.commit_group;");
            asm volatile("cp.async.wait_group 2;");
        } else if (t + 1 < T) {
            asm volatile("cp.async.wait_group 1;");
        } else {
            asm volatile("cp.async.wait_group 0;");
        }
        __syncthreads();

        const uint32_t sA = smb + (uint32_t)(s * STAGEH) * 2u;
        const uint32_t sB = sA + BM * LST * 2u;

        #pragma unroll
        for (int kk = 0; kk < 2; ++kk) {
            const int kb = kk * 16;
            uint32_t a[4][4], b[8][2];
            #pragma unroll
            for (int i = 0; i < 4; ++i)
                ldsm4(a[i], sA + (uint32_t)((wm * 64 + i * 16 + a_r) * LST + kb + a_k) * 2u);
            #pragma unroll
            for (int jp = 0; jp < 4; ++jp) {
                uint32_t r[4];
                ldsm4(r, sB + (uint32_t)((wn * 64 + (jp * 2 + b_t) * 8 + b_r) * LST + kb + b_k) * 2u);
                b[jp * 2][0] = r[0]; b[jp * 2][1] = r[1];
                b[jp * 2 + 1][0] = r[2]; b[jp * 2 + 1][1] = r[3];
            }
            #pragma unroll
            for (int i = 0; i < 4; ++i)
                #pragma unroll
                for (int j = 0; j < 8; ++j) mma_f16(acc[i][j], a[i], b[j]);
        }
        __syncthreads();
    }

    #pragma unroll
    for (int i = 0; i < 4; ++i) {
        int r = m0 + wm * 64 + i * 16 + g8;
        #pragma unroll
        for (int j = 0; j < 8; ++j) {
            int n = n0 + wn * 64 + j * 8 + tig * 2;
            float b0 = bias[n], b1 = bias[n + 1];
            float v0 = acc[i][j][0] + b0, v1 = acc[i][j][1] + b1;
            float v2 = acc[i][j][2] + b0, v3 = acc[i][j][3] + b1;
            long o0 = (long)r * N + n;
            long o1 = (long)(r + 8) * N + n;
            if (HAS_RES) {
                float2 r0 = *(const float2*)(res + o0);
                float2 r1 = *(const float2*)(res + o1);
                v0 += r0.x; v1 += r0.y; v2 += r1.x; v3 += r1.y;
            }
            if (OUT_HALF) {
                __half* out = (__half*)outv;
                *(__half2*)(out + o0) = __floats2half2_rn(v0, v1);
                *(__half2*)(out + o1) = __floats2half2_rn(v2, v3);
            } else {
                float* out = (float*)outv;
                *(float2*)(out + o0) = make_float2(v0, v1);
                *(float2*)(out + o1) = make_float2(v2, v3);
            }
        }
    }
}

// ---------------- Windowed attention: tensor-core QK^T and P*V ----------------------
// One block (128 thr, 4 warps) per (window, head). 49 padded to 64.
#define ALST 40     // q/k/v smem stride (halves)
#define PLST 72     // P smem stride (halves)
__global__ __launch_bounds__(128)
void attn_kernel(const __half* __restrict__ qkv, const float* __restrict__ rpb,
                 const float* __restrict__ x, float* __restrict__ x1) {
    const int head = blockIdx.x & 15;
    const int win  = blockIdx.x >> 4;
    const int b    = win >> 6;
    const int wi   = (win >> 3) & 7;
    const int wj   = win & 7;
    const int tid  = threadIdx.x;
    const int lane = tid & 31, w = tid >> 5;

    __shared__ __half qs[64 * ALST];
    __shared__ __half ks2[64 * ALST];
    __shared__ __half vs2[64 * ALST];
    __shared__ float  ss[64 * 65];
    __shared__ __half ps[64 * PLST];

    // load Q/K/V rows 0..48 (16 half2 each)
    for (int idx = tid; idx < WS2_ * 16; idx += 128) {
        int p = idx >> 4, d2 = idx & 15;
        int token = (wi * 7 + p / 7) * 56 + (wj * 7 + p % 7);
        long base = ((long)b * N_ + token) * THREEC_ + head * HD_ + 2 * d2;
        *(__half2*)&qs[p * ALST + 2 * d2]  = *(const __half2*)(qkv + base);
        *(__half2*)&ks2[p * ALST + 2 * d2] = *(const __half2*)(qkv + base + C_);
        *(__half2*)&vs2[p * ALST + 2 * d2] = *(const __half2*)(qkv + base + 2 * C_);
    }
    // zero V pad rows 49..63 (16 half2 per row)
    for (int idx = tid; idx < 15 * 16; idx += 128) {
        int r = 49 + idx / 16, c2 = idx % 16;
        *(__half2*)&vs2[r * ALST + 2 * c2] = __floats2half2_rn(0.f, 0.f);
    }
    __syncthreads();

    const uint32_t qb = (uint32_t)__cvta_generic_to_shared(qs);
    const uint32_t kb2 = (uint32_t)__cvta_generic_to_shared(ks2);
    const uint32_t vb = (uint32_t)__cvta_generic_to_shared(vs2);
    const uint32_t pb = (uint32_t)__cvta_generic_to_shared(ps);

    const int a_r = (lane & 15), a_k = (lane >> 4) * 8;
    const int b_r = lane & 7, b_t = (lane >> 4), b_k = ((lane >> 3) & 1) * 8;
    const int g8 = lane >> 2, tig = lane & 3;
    const float scale = 0.17677669529663687f;

    // ---- S = Q K^T : each warp computes rows [w*16, w*16+16) x 64 cols ----
    {
        float acc[8][4];
        #pragma unroll
        for (int j = 0; j < 8; ++j)
            #pragma unroll
            for (int t = 0; t < 4; ++t) acc[j][t] = 0.0f;

        #pragma unroll
        for (int kk = 0; kk < 2; ++kk) {
            const int kbo = kk * 16;
            uint32_t a[4];
            ldsm4(a, qb + (uint32_t)((w * 16 + a_r) * ALST + kbo + a_k) * 2u);
            #pragma unroll
            for (int jp = 0; jp < 4; ++jp) {
                uint32_t r[4];
                ldsm4(r, kb2 + (uint32_t)(((jp * 2 + b_t) * 8 + b_r) * ALST + kbo + b_k) * 2u);
                uint32_t b0[2] = {r[0], r[1]}, b1[2] = {r[2], r[3]};
                mma_f16(acc[jp * 2], a, b0);
                mma_f16(acc[jp * 2 + 1], a, b1);
            }
        }
        // epilogue: scale + rel-pos bias, write valid entries of S
        #pragma unroll
        for (int jt = 0; jt < 8; ++jt) {
            #pragma unroll
            for (int h = 0; h < 2; ++h) {
                int i = w * 16 + g8 + h * 8;
                if (i < WS2_) {
                    int j0 = jt * 8 + tig * 2;
                    #pragma unroll
                    for (int e = 0; e < 2; ++e) {
                        int j = j0 + e;
                        if (j < WS2_) {
                            int dpi = (i / 7) - (j / 7) + 6;
                            int dpj = (i % 7) - (j % 7) + 6;
                            ss[i * 65 + j] = acc[jt][h * 2 + e] * scale
                                           + rpb[(dpi * 13 + dpj) * NH_ + head];
                        }
                    }
                }
            }
        }
    }
    __syncthreads();

    // ---- softmax rows 0..48; write P (half) with zero pad cols ----
    if (tid < WS2_) {
        float mx = -1e30f;
        #pragma unroll
        for (int j = 0; j < WS2_; ++j) mx = fmaxf(mx, ss[tid * 65 + j]);
        float sum = 0.0f;
        float e[WS2_];
        #pragma unroll
        for (int j = 0; j < WS2_; ++j) { e[j] = __expf(ss[tid * 65 + j] - mx); sum += e[j]; }
        float inv = 1.0f / sum;
        #pragma unroll
        for (int j = 0; j < WS2_; ++j) ps[tid * PLST + j] = __float2half_rn(e[j] * inv);
        #pragma unroll
        for (int j = WS2_; j < 64; ++j) ps[tid * PLST + j] = __ushort_as_half(0);
    } else if (tid < 64) {
        // zero pad P rows 49..63 (feeds only unused O rows, but avoid NaN surprises)
        for (int j = 0; j < 64; ++j) ps[tid * PLST + j] = __ushort_as_half(0);
    }
    __syncthreads();

    // ---- O = P V : each warp computes rows [w*16, +16) x 32 cols ----
    {
        float oacc[4][4];
        #pragma unroll
        for (int j = 0; j < 4; ++j)
            #pragma unroll
            for (int t = 0; t < 4; ++t) oacc[j][t] = 0.0f;

        const int tr = (lane & 7) + ((lane >> 3) & 1) * 8;   // row within 16-k block
        const int tc = (lane >> 4) * 8;                      // col offset 0/8

        #pragma unroll
        for (int ks_ = 0; ks_ < 4; ++ks_) {
            const int kbo = ks_ * 16;
            uint32_t a[4];
            ldsm4(a, pb + (uint32_t)((w * 16 + a_r) * PLST + kbo + a_k) * 2u);
            #pragma unroll
            for (int dp = 0; dp < 2; ++dp) {
                uint32_t r[4];
                ldsm4t(r, vb + (uint32_t)((kbo + tr) * ALST + dp * 16 + tc) * 2u);
                uint32_t b0[2] = {r[0], r[1]}, b1[2] = {r[2], r[3]};
                mma_f16(oacc[dp * 2], a, b0);
                mma_f16(oacc[dp * 2 + 1], a, b1);
            }
        }
        // write O + residual
        #pragma unroll
        for (int h = 0; h < 2; ++h) {
            int i = w * 16 + g8 + h * 8;
            if (i < WS2_) {
                int token = (wi * 7 + i / 7) * 56 + (wj * 7 + i % 7);
                long ob = ((long)b * N_ + token) * C_ + head * HD_;
                #pragma unroll
                for (int dt = 0; dt < 4; ++dt) {
                    int d0 = dt * 8 + tig * 2;
                    long o = ob + d0;
                    float2 xv = *(const float2*)(x + o);
                    float2 ov;
                    ov.x = xv.x + oacc[dt][h * 2];
                    ov.y = xv.y + oacc[dt][h * 2 + 1];
                    *(float2*)(x1 + o) = ov;
                }
            }
        }
    }
}

// ---------------- depthwise 3x3 + GELU: 8-row strip, sliding window ------------------
__global__ __launch_bounds__(256)
void dwconv_gelu_kernel(const __half2* __restrict__ h2, const float* __restrict__ w,
                        const float* __restrict__ bias, __half2* __restrict__ out) {
    __shared__ float ws[512 * 9];
    const int bid = blockIdx.x;
    const int chunk = bid & 3;
    const int strip = (bid >> 2) % 7;
    const int bb = (bid >> 2) / 7;
    const int r0 = strip * 8;
    const int cp = chunk * 256 + threadIdx.x;

    for (int q = threadIdx.x; q < 512 * 9; q += 256)
        ws[q] = w[(long)(chunk * 512) * 9 + q];
    __syncthreads();

    float wr[18];
    #pragma unroll
    for (int t = 0; t < 18; ++t) wr[t] = ws[(2 * threadIdx.x) * 9 + t];
    const int c = cp * 2;
    const float bi0 = bias[c], bi1 = bias[c + 1];

    long rb[10];
    bool rv[10];
    #pragma unroll
    for (int j = 0; j < 10; ++j) {
        int r = r0 - 1 + j;
        rv[j] = (r >= 0 && r < 56);
        rb[j] = (((long)bb * 56 + (rv[j] ? r : 0)) * 56) * 1024 + cp;
    }

    float2 col[3][10];
    #pragma unroll
    for (int j = 0; j < 10; ++j) {
        col[0][j] = make_float2(0.f, 0.f);
        col[1][j] = rv[j] ? __half22float2(h2[rb[j]]) : make_float2(0.f, 0.f);
    }

    for (int wcol = 0; wcol < 56; ++wcol) {
        if (wcol + 1 < 56) {
            long o = (long)(wcol + 1) * 1024;
            #pragma unroll
            for (int j = 0; j < 10; ++j)
                col[2][j] = rv[j] ? __half22float2(h2[rb[j] + o]) : make_float2(0.f, 0.f);
        } else {
            #pragma unroll
            for (int j = 0; j < 10; ++j) col[2][j] = make_float2(0.f, 0.f);
        }

        #pragma unroll
        for (int rr = 0; rr < 8; ++rr) {
            float a0 = bi0, a1 = bi1;
            #pragma unroll
            for (int dy = 0; dy < 3; ++dy) {
                #pragma unroll
                for (int dx = 0; dx < 3; ++dx) {
                    float2 vv = col[dx][rr + dy];
                    a0 = fmaf(vv.x, wr[dy * 3 + dx], a0);
                    a1 = fmaf(vv.y, wr[9 + dy * 3 + dx], a1);
                }
            }
            float g0 = 0.5f * a0 * (1.0f + erff(a0 * 0.70710678118654752f));
            float g1 = 0.5f * a1 * (1.0f + erff(a1 * 0.70710678118654752f));
            out[(((long)bb * 56 + (r0 + rr)) * 56 + wcol) * 1024 + cp] = __floats2half2_rn(g0, g1);
        }

        #pragma unroll
        for (int j = 0; j < 10; ++j) { col[0][j] = col[1][j]; col[1][j] = col[2][j]; }
    }
}

// ---------------- launch ----------------
extern "C" void kernel_launch(void* const* d_in, const int* in_sizes, int n_in,
                              void* d_out, int out_size) {
    const float* x       = (const float*)d_in[0];
    const float* norm1_g = (const float*)d_in[3];
    const float* norm1_b = (const float*)d_in[4];
    const float* norm2_g = (const float*)d_in[5];
    const float* norm2_b = (const float*)d_in[6];
    const float* qkv_w   = (const float*)d_in[7];
    const float* qkv_b   = (const float*)d_in[8];
    const float* rpb     = (const float*)d_in[9];
    const float* fc1_w   = (const float*)d_in[10];
    const float* fc1_b   = (const float*)d_in[11];
    const float* dw_w    = (const float*)d_in[12];
    const float* dw_b    = (const float*)d_in[13];
    const float* fc2_w   = (const float*)d_in[14];
    const float* fc2_b   = (const float*)d_in[15];
    float* out = (float*)d_out;

    __half *p_hh, *p_qkvh, *p_h2h, *p_h3h, *p_wq, *p_wf1, *p_wf2;
    float *p_x1;
    cudaGetSymbolAddress((void**)&p_hh,   g_hh);
    cudaGetSymbolAddress((void**)&p_qkvh, g_qkvh);
    cudaGetSymbolAddress((void**)&p_x1,   g_x1);
    cudaGetSymbolAddress((void**)&p_h2h,  g_h2h);
    cudaGetSymbolAddress((void**)&p_h3h,  g_h3h);
    cudaGetSymbolAddress((void**)&p_wq,   g_wq);
    cudaGetSymbolAddress((void**)&p_wf1,  g_wf1);
    cudaGetSymbolAddress((void**)&p_wf2,  g_wf2);

    cudaFuncSetAttribute(gemm_h_kernel<true, false>,
                         cudaFuncAttributeMaxDynamicSharedMemorySize, GSMEM);
    cudaFuncSetAttribute(gemm_h_kernel<false, true>,
                         cudaFuncAttributeMaxDynamicSharedMemorySize, GSMEM);

    // 0) weight conversions (one fused launch)
    f2h_all_kernel<<<F2H_N1 + F2H_N2 + F2H_N3, 256>>>(
        (const float4*)qkv_w, (const float4*)fc1_w, (const float4*)fc2_w,
        (__half2*)p_wq, (__half2*)p_wf1, (__half2*)p_wf2);

    // 1) LN1
    ln_kernel<<<TOK_ / 8, 256>>>(x, norm1_g, norm1_b, p_hh);
    // 2) QKV GEMM
    gemm_h_kernel<true, false><<<dim3(THREEC_ / BN, TOK_ / BM), 128, GSMEM>>>(
        p_hh, p_wq, qkv_b, nullptr, p_qkvh, TOK_, THREEC_, C_);
    // 3) windowed attention (tensor-core) + residual
    attn_kernel<<<B_ * 64 * NH_, 128>>>(p_qkvh, rpb, x, p_x1);
    // 4) LN2
    ln_kernel<<<TOK_ / 8, 256>>>(p_x1, norm2_g, norm2_b, p_hh);
    // 5) fc1 GEMM
    gemm_h_kernel<true, false><<<dim3(HID_ / BN, TOK_ / BM), 128, GSMEM>>>(
        p_hh, p_wf1, fc1_b, nullptr, p_h2h, TOK_, HID_, C_);
    // 6) depthwise conv + GELU (8-row strips)
    dwconv_gelu_kernel<<<B_ * 7 * 4, 256>>>(
        (const __half2*)p_h2h, dw_w, dw_b, (__half2*)p_h3h);
    // 7) fc2 GEMM + residual -> out
    gemm_h_kernel<false, true><<<dim3(C_ / BN, TOK_ / BM), 128, GSMEM>>>(
        p_h3h, p_wf2, fc2_b, p_x1, out, TOK_, C_, HID_);
}

// round 17
// speedup vs baseline: 1.4565x; 1.0504x over previous
#include <cuda_runtime.h>
#include <cuda_fp16.h>
#include <math.h>
#include <stdint.h>

// ---------------- problem constants ----------------
#define B_   8
#define HH_  56
#define WW_  56
#define N_   (HH_*WW_)          // 3136
#define C_   512
#define NH_  16
#define HD_  32
#define WS_  7
#define WS2_ 49
#define HID_ 2048
#define TOK_ (B_*N_)            // 25088
#define THREEC_ (3*C_)          // 1536

// ---------------- scratch ----------------
static __device__ __half g_hh  [(size_t)TOK_*C_];
static __device__ __half g_qkvh[(size_t)TOK_*THREEC_];
static __device__ float  g_x1  [(size_t)TOK_*C_];
static __device__ __half g_h2h [(size_t)TOK_*HID_];
static __device__ __half g_h3h [(size_t)TOK_*HID_];
static __device__ __half g_wq  [(size_t)THREEC_*C_];
static __device__ __half g_wf1 [(size_t)HID_*C_];
static __device__ __half g_wf2 [(size_t)C_*HID_];

// ---------------- fused fp32 -> fp16 conversion ----------------
#define F2H_N1 (THREEC_ * C_ / 4 / 256)
#define F2H_N2 (HID_ * C_ / 4 / 256)
#define F2H_N3 (C_ * HID_ / 4 / 256)
__global__ __launch_bounds__(256)
void f2h_all_kernel(const float4* __restrict__ w0, const float4* __restrict__ w1,
                    const float4* __restrict__ w2, __half2* __restrict__ o0,
                    __half2* __restrict__ o1, __half2* __restrict__ o2) {
    int bid = blockIdx.x;
    const float4* in;
    __half2* out;
    int base;
    if (bid < F2H_N1) { in = w0; out = o0; base = bid; }
    else if (bid < F2H_N1 + F2H_N2) { in = w1; out = o1; base = bid - F2H_N1; }
    else { in = w2; out = o2; base = bid - F2H_N1 - F2H_N2; }
    int i = base * 256 + threadIdx.x;
    float4 v = in[i];
    out[2 * i]     = __floats2half2_rn(v.x, v.y);
    out[2 * i + 1] = __floats2half2_rn(v.z, v.w);
}

// ---------------- LayerNorm: warp per row ----------------
__global__ __launch_bounds__(256)
void ln_kernel(const float* __restrict__ x, const float* __restrict__ g,
               const float* __restrict__ b, __half* __restrict__ out) {
    __shared__ float sg[C_], sb[C_];
    const int tid = threadIdx.x;
    sg[tid] = g[tid]; sg[tid + 256] = g[tid + 256];
    sb[tid] = b[tid]; sb[tid + 256] = b[tid + 256];
    __syncthreads();

    const int lane = tid & 31, wid = tid >> 5;
    const long row = (long)blockIdx.x * 8 + wid;
    const float4* xr = (const float4*)(x + row * C_);

    float4 v[4];
    float sum = 0.0f;
    #pragma unroll
    for (int k = 0; k < 4; ++k) {
        v[k] = xr[lane + k * 32];
        sum += v[k].x + v[k].y + v[k].z + v[k].w;
    }
    #pragma unroll
    for (int o = 16; o > 0; o >>= 1) sum += __shfl_xor_sync(0xffffffffu, sum, o);
    float mu = sum * (1.0f / C_);

    float vs = 0.0f;
    #pragma unroll
    for (int k = 0; k < 4; ++k) {
        float dx = v[k].x - mu, dy = v[k].y - mu, dz = v[k].z - mu, dw = v[k].w - mu;
        vs += dx * dx + dy * dy + dz * dz + dw * dw;
    }
    #pragma unroll
    for (int o = 16; o > 0; o >>= 1) vs += __shfl_xor_sync(0xffffffffu, vs, o);
    float inv = rsqrtf(vs * (1.0f / C_) + 1e-5f);

    __half2* orow = (__half2*)(out + row * C_);
    #pragma unroll
    for (int k = 0; k < 4; ++k) {
        int i4 = lane + k * 32, c = i4 * 4;
        float e0 = (v[k].x - mu) * inv * sg[c]     + sb[c];
        float e1 = (v[k].y - mu) * inv * sg[c + 1] + sb[c + 1];
        float e2 = (v[k].z - mu) * inv * sg[c + 2] + sb[c + 2];
        float e3 = (v[k].w - mu) * inv * sg[c + 3] + sb[c + 3];
        orow[i4 * 2]     = __floats2half2_rn(e0, e1);
        orow[i4 * 2 + 1] = __floats2half2_rn(e2, e3);
    }
}

// ---------------- shared PTX primitives ----------------
__device__ __forceinline__ void cpa16(uint32_t s, const void* g) {
    asm volatile("cp.async.ca.shared.global [%0], [%1], 16;" :: "r"(s), "l"(g));
}
__device__ __forceinline__ void ldsm4(uint32_t* r, uint32_t addr) {
    asm volatile("ldmatrix.sync.aligned.m8n8.x4.shared.b16 {%0,%1,%2,%3}, [%4];"
                 : "=r"(r[0]), "=r"(r[1]), "=r"(r[2]), "=r"(r[3]) : "r"(addr));
}
__device__ __forceinline__ void ldsm4t(uint32_t* r, uint32_t addr) {
    asm volatile("ldmatrix.sync.aligned.m8n8.x4.trans.shared.b16 {%0,%1,%2,%3}, [%4];"
                 : "=r"(r[0]), "=r"(r[1]), "=r"(r[2]), "=r"(r[3]) : "r"(addr));
}
__device__ __forceinline__ void mma_f16(float* c, const uint32_t* a, const uint32_t* b) {
    asm volatile(
        "mma.sync.aligned.m16n8k16.row.col.f32.f16.f16.f32 "
        "{%0,%1,%2,%3}, {%4,%5,%6,%7}, {%8,%9}, {%0,%1,%2,%3};"
        : "+f"(c[0]), "+f"(c[1]), "+f"(c[2]), "+f"(c[3])
        : "r"(a[0]), "r"(a[1]), "r"(a[2]), "r"(a[3]), "r"(b[0]), "r"(b[1]));
}

// ---------------- FP16 GEMM: 128x128 CTA, 4 warps 64x64, 3-stage (R6 exact) ---------
#define BM 128
#define BN 128
#define BKH 32
#define LST 40
#define STAGEH ((BM + BN) * LST)
#define GSMEM (3 * STAGEH * 2)

template<bool OUT_HALF, bool HAS_RES>
__global__ __launch_bounds__(128, 2)
void gemm_h_kernel(const __half* __restrict__ A, const __half* __restrict__ Bm,
                   const float* __restrict__ bias, const float* __restrict__ res,
                   void* __restrict__ outv, int M, int N, int K) {
    extern __shared__ __half sm[];
    const uint32_t smb = (uint32_t)__cvta_generic_to_shared(sm);
    const int tid = threadIdx.x;
    const int lane = tid & 31, wid = tid >> 5;
    const int wm = wid & 1, wn = wid >> 1;
    const int g8 = lane >> 2, tig = lane & 3;
    const int m0 = blockIdx.y * BM, n0 = blockIdx.x * BN;

    float acc[4][8][4];
    #pragma unroll
    for (int i = 0; i < 4; ++i)
        #pragma unroll
        for (int j = 0; j < 8; ++j)
            #pragma unroll
            for (int t = 0; t < 4; ++t) acc[i][j][t] = 0.0f;

    const int T = K / BKH;
    const int lrow = tid >> 2, lq = tid & 3;

    auto load_stage = [&](int t, int s) {
        const int k0 = t * BKH;
        #pragma unroll
        for (int i = 0; i < 4; ++i) {
            int row = lrow + i * 32;
            uint32_t sa = smb + (uint32_t)(s * STAGEH + row * LST + lq * 8) * 2u;
            cpa16(sa, A + (long)(m0 + row) * K + k0 + lq * 8);
            cpa16(sa + BM * LST * 2u, Bm + (long)(n0 + row) * K + k0 + lq * 8);
        }
    };

    load_stage(0, 0);
    asm volatile("cp.async.commit_group;");
    if (T > 1) { load_stage(1, 1); asm volatile("cp.async.commit_group;"); }

    const int a_r = (lane & 15), a_k = (lane >> 4) * 8;
    const int b_r = (lane & 7), b_t = (lane >> 4), b_k = ((lane >> 3) & 1) * 8;

    for (int t = 0; t < T; ++t) {
        const int s = t % 3;
        if (t + 2 < T) {
            load_stage(t + 2, (t + 2) % 3);
            asm volatile("cp.async.commit_group;");
            asm volatile("cp.async.wait_group 2;");
        } else if (t + 1 < T) {
            asm volatile("cp.async.wait_group 1;");
        } else {
            asm volatile("cp.async.wait_group 0;");
        }
        __syncthreads();

        const uint32_t sA = smb + (uint32_t)(s * STAGEH) * 2u;
        const uint32_t sB = sA + BM * LST * 2u;

        #pragma unroll
        for (int kk = 0; kk < 2; ++kk) {
            const int kb = kk * 16;
            uint32_t a[4][4], b[8][2];
            #pragma unroll
            for (int i = 0; i < 4; ++i)
                ldsm4(a[i], sA + (uint32_t)((wm * 64 + i * 16 + a_r) * LST + kb + a_k) * 2u);
            #pragma unroll
            for (int jp = 0; jp < 4; ++jp) {
                uint32_t r[4];
                ldsm4(r, sB + (uint32_t)((wn * 64 + (jp * 2 + b_t) * 8 + b_r) * LST + kb + b_k) * 2u);
                b[jp * 2][0] = r[0]; b[jp * 2][1] = r[1];
                b[jp * 2 + 1][0] = r[2]; b[jp * 2 + 1][1] = r[3];
            }
            #pragma unroll
            for (int i = 0; i < 4; ++i)
                #pragma unroll
                for (int j = 0; j < 8; ++j) mma_f16(acc[i][j], a[i], b[j]);
        }
        __syncthreads();
    }

    #pragma unroll
    for (int i = 0; i < 4; ++i) {
        int r = m0 + wm * 64 + i * 16 + g8;
        #pragma unroll
        for (int j = 0; j < 8; ++j) {
            int n = n0 + wn * 64 + j * 8 + tig * 2;
            float b0 = bias[n], b1 = bias[n + 1];
            float v0 = acc[i][j][0] + b0, v1 = acc[i][j][1] + b1;
            float v2 = acc[i][j][2] + b0, v3 = acc[i][j][3] + b1;
            long o0 = (long)r * N + n;
            long o1 = (long)(r + 8) * N + n;
            if (HAS_RES) {
                float2 r0 = *(const float2*)(res + o0);
                float2 r1 = *(const float2*)(res + o1);
                v0 += r0.x; v1 += r0.y; v2 += r1.x; v3 += r1.y;
            }
            if (OUT_HALF) {
                __half* out = (__half*)outv;
                *(__half2*)(out + o0) = __floats2half2_rn(v0, v1);
                *(__half2*)(out + o1) = __floats2half2_rn(v2, v3);
            } else {
                float* out = (float*)outv;
                *(float2*)(out + o0) = make_float2(v0, v1);
                *(float2*)(out + o1) = make_float2(v2, v3);
            }
        }
    }
}

// ---------------- Windowed attention: tensor-core QK^T and P*V ----------------------
// One block (128 thr, 4 warps) per (window, head). 49 padded to 64 where needed.
#define ALST 40     // q/k/v smem stride (halves)
#define PLST 72     // P smem stride (halves)
#define SST  50     // score smem stride (floats)
__global__ __launch_bounds__(128)
void attn_kernel(const __half* __restrict__ qkv, const float* __restrict__ rpb,
                 const float* __restrict__ x, float* __restrict__ x1) {
    const int head = blockIdx.x & 15;
    const int win  = blockIdx.x >> 4;
    const int b    = win >> 6;
    const int wi   = (win >> 3) & 7;
    const int wj   = win & 7;
    const int tid  = threadIdx.x;
    const int lane = tid & 31, w = tid >> 5;

    __shared__ __align__(16) __half qs[64 * ALST];
    __shared__ __align__(16) __half ks2[64 * ALST];
    __shared__ __align__(16) __half vs2[64 * ALST];
    __shared__ __align__(16) float  ss[WS2_ * SST];
    __shared__ __align__(16) __half ps[64 * PLST];
    __shared__ __align__(16) float  sbias[169];

    // per-head rel-pos bias table -> smem
    for (int idx = tid; idx < 169; idx += 128) sbias[idx] = rpb[idx * NH_ + head];

    // load Q/K/V rows 0..48 (16 half2 each)
    for (int idx = tid; idx < WS2_ * 16; idx += 128) {
        int p = idx >> 4, d2 = idx & 15;
        int token = (wi * 7 + p / 7) * 56 + (wj * 7 + p % 7);
        long base = ((long)b * N_ + token) * THREEC_ + head * HD_ + 2 * d2;
        *(__half2*)&qs[p * ALST + 2 * d2]  = *(const __half2*)(qkv + base);
        *(__half2*)&ks2[p * ALST + 2 * d2] = *(const __half2*)(qkv + base + C_);
        *(__half2*)&vs2[p * ALST + 2 * d2] = *(const __half2*)(qkv + base + 2 * C_);
    }
    // zero V pad rows 49..63
    for (int idx = tid; idx < 15 * 16; idx += 128) {
        int r = 49 + idx / 16, c2 = idx % 16;
        *(__half2*)&vs2[r * ALST + 2 * c2] = __floats2half2_rn(0.f, 0.f);
    }
    __syncthreads();

    const uint32_t qb = (uint32_t)__cvta_generic_to_shared(qs);
    const uint32_t kb2 = (uint32_t)__cvta_generic_to_shared(ks2);
    const uint32_t vb = (uint32_t)__cvta_generic_to_shared(vs2);
    const uint32_t pb = (uint32_t)__cvta_generic_to_shared(ps);

    const int a_r = (lane & 15), a_k = (lane >> 4) * 8;
    const int b_r = lane & 7, b_t = (lane >> 4), b_k = ((lane >> 3) & 1) * 8;
    const int g8 = lane >> 2, tig = lane & 3;
    const float scale = 0.17677669529663687f;

    // ---- S = Q K^T : each warp computes rows [w*16, w*16+16) x 64 cols ----
    {
        float acc[8][4];
        #pragma unroll
        for (int j = 0; j < 8; ++j)
            #pragma unroll
            for (int t = 0; t < 4; ++t) acc[j][t] = 0.0f;

        #pragma unroll
        for (int kk = 0; kk < 2; ++kk) {
            const int kbo = kk * 16;
            uint32_t a[4];
            ldsm4(a, qb + (uint32_t)((w * 16 + a_r) * ALST + kbo + a_k) * 2u);
            #pragma unroll
            for (int jp = 0; jp < 4; ++jp) {
                uint32_t r[4];
                ldsm4(r, kb2 + (uint32_t)(((jp * 2 + b_t) * 8 + b_r) * ALST + kbo + b_k) * 2u);
                uint32_t b0[2] = {r[0], r[1]}, b1[2] = {r[2], r[3]};
                mma_f16(acc[jp * 2], a, b0);
                mma_f16(acc[jp * 2 + 1], a, b1);
            }
        }
        // epilogue: scale + rel-pos bias (smem table), write valid entries of S
        #pragma unroll
        for (int jt = 0; jt < 8; ++jt) {
            #pragma unroll
            for (int h = 0; h < 2; ++h) {
                int i = w * 16 + g8 + h * 8;
                if (i < WS2_) {
                    int j0 = jt * 8 + tig * 2;
                    #pragma unroll
                    for (int e = 0; e < 2; ++e) {
                        int j = j0 + e;
                        if (j < WS2_) {
                            int dpi = (i / 7) - (j / 7) + 6;
                            int dpj = (i % 7) - (j % 7) + 6;
                            ss[i * SST + j] = acc[jt][h * 2 + e] * scale
                                            + sbias[dpi * 13 + dpj];
                        }
                    }
                }
            }
        }
    }
    __syncthreads();

    // ---- softmax rows 0..48; write P (half) with zero pad cols ----
    if (tid < WS2_) {
        float mx = -1e30f;
        #pragma unroll
        for (int j = 0; j < WS2_; ++j) mx = fmaxf(mx, ss[tid * SST + j]);
        float sum = 0.0f;
        float e[WS2_];
        #pragma unroll
        for (int j = 0; j < WS2_; ++j) { e[j] = __expf(ss[tid * SST + j] - mx); sum += e[j]; }
        float inv = 1.0f / sum;
        #pragma unroll
        for (int j = 0; j < WS2_; ++j) ps[tid * PLST + j] = __float2half_rn(e[j] * inv);
        #pragma unroll
        for (int j = WS2_; j < 64; ++j) ps[tid * PLST + j] = __ushort_as_half(0);
    } else if (tid < 64) {
        for (int j = 0; j < 64; ++j) ps[tid * PLST + j] = __ushort_as_half(0);
    }
    __syncthreads();

    // ---- O = P V : each warp computes rows [w*16, +16) x 32 cols ----
    {
        float oacc[4][4];
        #pragma unroll
        for (int j = 0; j < 4; ++j)
            #pragma unroll
            for (int t = 0; t < 4; ++t) oacc[j][t] = 0.0f;

        const int tr = (lane & 7) + ((lane >> 3) & 1) * 8;
        const int tc = (lane >> 4) * 8;

        #pragma unroll
        for (int ks_ = 0; ks_ < 4; ++ks_) {
            const int kbo = ks_ * 16;
            uint32_t a[4];
            ldsm4(a, pb + (uint32_t)((w * 16 + a_r) * PLST + kbo + a_k) * 2u);
            #pragma unroll
            for (int dp = 0; dp < 2; ++dp) {
                uint32_t r[4];
                ldsm4t(r, vb + (uint32_t)((kbo + tr) * ALST + dp * 16 + tc) * 2u);
                uint32_t b0[2] = {r[0], r[1]}, b1[2] = {r[2], r[3]};
                mma_f16(oacc[dp * 2], a, b0);
                mma_f16(oacc[dp * 2 + 1], a, b1);
            }
        }
        // write O + residual
        #pragma unroll
        for (int h = 0; h < 2; ++h) {
            int i = w * 16 + g8 + h * 8;
            if (i < WS2_) {
                int token = (wi * 7 + i / 7) * 56 + (wj * 7 + i % 7);
                long ob = ((long)b * N_ + token) * C_ + head * HD_;
                #pragma unroll
                for (int dt = 0; dt < 4; ++dt) {
                    int d0 = dt * 8 + tig * 2;
                    long o = ob + d0;
                    float2 xv = *(const float2*)(x + o);
                    float2 ov;
                    ov.x = xv.x + oacc[dt][h * 2];
                    ov.y = xv.y + oacc[dt][h * 2 + 1];
                    *(float2*)(x1 + o) = ov;
                }
            }
        }
    }
}

// ---------------- depthwise 3x3 + GELU: 8-row strip, sliding window ------------------
__global__ __launch_bounds__(256)
void dwconv_gelu_kernel(const __half2* __restrict__ h2, const float* __restrict__ w,
                        const float* __restrict__ bias, __half2* __restrict__ out) {
    __shared__ float ws[512 * 9];
    const int bid = blockIdx.x;
    const int chunk = bid & 3;
    const int strip = (bid >> 2) % 7;
    const int bb = (bid >> 2) / 7;
    const int r0 = strip * 8;
    const int cp = chunk * 256 + threadIdx.x;

    for (int q = threadIdx.x; q < 512 * 9; q += 256)
        ws[q] = w[(long)(chunk * 512) * 9 + q];
    __syncthreads();

    float wr[18];
    #pragma unroll
    for (int t = 0; t < 18; ++t) wr[t] = ws[(2 * threadIdx.x) * 9 + t];
    const int c = cp * 2;
    const float bi0 = bias[c], bi1 = bias[c + 1];

    long rb[10];
    bool rv[10];
    #pragma unroll
    for (int j = 0; j < 10; ++j) {
        int r = r0 - 1 + j;
        rv[j] = (r >= 0 && r < 56);
        rb[j] = (((long)bb * 56 + (rv[j] ? r : 0)) * 56) * 1024 + cp;
    }

    float2 col[3][10];
    #pragma unroll
    for (int j = 0; j < 10; ++j) {
        col[0][j] = make_float2(0.f, 0.f);
        col[1][j] = rv[j] ? __half22float2(h2[rb[j]]) : make_float2(0.f, 0.f);
    }

    for (int wcol = 0; wcol < 56; ++wcol) {
        if (wcol + 1 < 56) {
            long o = (long)(wcol + 1) * 1024;
            #pragma unroll
            for (int j = 0; j < 10; ++j)
                col[2][j] = rv[j] ? __half22float2(h2[rb[j] + o]) : make_float2(0.f, 0.f);
        } else {
            #pragma unroll
            for (int j = 0; j < 10; ++j) col[2][j] = make_float2(0.f, 0.f);
        }

        #pragma unroll
        for (int rr = 0; rr < 8; ++rr) {
            float a0 = bi0, a1 = bi1;
            #pragma unroll
            for (int dy = 0; dy < 3; ++dy) {
                #pragma unroll
                for (int dx = 0; dx < 3; ++dx) {
                    float2 vv = col[dx][rr + dy];
                    a0 = fmaf(vv.x, wr[dy * 3 + dx], a0);
                    a1 = fmaf(vv.y, wr[9 + dy * 3 + dx], a1);
                }
            }
            float g0 = 0.5f * a0 * (1.0f + erff(a0 * 0.70710678118654752f));
            float g1 = 0.5f * a1 * (1.0f + erff(a1 * 0.70710678118654752f));
            out[(((long)bb * 56 + (r0 + rr)) * 56 + wcol) * 1024 + cp] = __floats2half2_rn(g0, g1);
        }

        #pragma unroll
        for (int j = 0; j < 10; ++j) { col[0][j] = col[1][j]; col[1][j] = col[2][j]; }
    }
}

// ---------------- launch ----------------
extern "C" void kernel_launch(void* const* d_in, const int* in_sizes, int n_in,
                              void* d_out, int out_size) {
    const float* x       = (const float*)d_in[0];
    const float* norm1_g = (const float*)d_in[3];
    const float* norm1_b = (const float*)d_in[4];
    const float* norm2_g = (const float*)d_in[5];
    const float* norm2_b = (const float*)d_in[6];
    const float* qkv_w   = (const float*)d_in[7];
    const float* qkv_b   = (const float*)d_in[8];
    const float* rpb     = (const float*)d_in[9];
    const float* fc1_w   = (const float*)d_in[10];
    const float* fc1_b   = (const float*)d_in[11];
    const float* dw_w    = (const float*)d_in[12];
    const float* dw_b    = (const float*)d_in[13];
    const float* fc2_w   = (const float*)d_in[14];
    const float* fc2_b   = (const float*)d_in[15];
    float* out = (float*)d_out;

    __half *p_hh, *p_qkvh, *p_h2h, *p_h3h, *p_wq, *p_wf1, *p_wf2;
    float *p_x1;
    cudaGetSymbolAddress((void**)&p_hh,   g_hh);
    cudaGetSymbolAddress((void**)&p_qkvh, g_qkvh);
    cudaGetSymbolAddress((void**)&p_x1,   g_x1);
    cudaGetSymbolAddress((void**)&p_h2h,  g_h2h);
    cudaGetSymbolAddress((void**)&p_h3h,  g_h3h);
    cudaGetSymbolAddress((void**)&p_wq,   g_wq);
    cudaGetSymbolAddress((void**)&p_wf1,  g_wf1);
    cudaGetSymbolAddress((void**)&p_wf2,  g_wf2);

    cudaFuncSetAttribute(gemm_h_kernel<true, false>,
                         cudaFuncAttributeMaxDynamicSharedMemorySize, GSMEM);
    cudaFuncSetAttribute(gemm_h_kernel<false, true>,
                         cudaFuncAttributeMaxDynamicSharedMemorySize, GSMEM);

    // 0) weight conversions (one fused launch)
    f2h_all_kernel<<<F2H_N1 + F2H_N2 + F2H_N3, 256>>>(
        (const float4*)qkv_w, (const float4*)fc1_w, (const float4*)fc2_w,
        (__half2*)p_wq, (__half2*)p_wf1, (__half2*)p_wf2);

    // 1) LN1
    ln_kernel<<<TOK_ / 8, 256>>>(x, norm1_g, norm1_b, p_hh);
    // 2) QKV GEMM
    gemm_h_kernel<true, false><<<dim3(THREEC_ / BN, TOK_ / BM), 128, GSMEM>>>(
        p_hh, p_wq, qkv_b, nullptr, p_qkvh, TOK_, THREEC_, C_);
    // 3) windowed attention (tensor-core) + residual
    attn_kernel<<<B_ * 64 * NH_, 128>>>(p_qkvh, rpb, x, p_x1);
    // 4) LN2
    ln_kernel<<<TOK_ / 8, 256>>>(p_x1, norm2_g, norm2_b, p_hh);
    // 5) fc1 GEMM
    gemm_h_kernel<true, false><<<dim3(HID_ / BN, TOK_ / BM), 128, GSMEM>>>(
        p_hh, p_wf1, fc1_b, nullptr, p_h2h, TOK_, HID_, C_);
    // 6) depthwise conv + GELU (8-row strips)
    dwconv_gelu_kernel<<<B_ * 7 * 4, 256>>>(
        (const __half2*)p_h2h, dw_w, dw_b, (__half2*)p_h3h);
    // 7) fc2 GEMM + residual -> out
    gemm_h_kernel<false, true><<<dim3(C_ / BN, TOK_ / BM), 128, GSMEM>>>(
        p_h3h, p_wf2, fc2_b, p_x1, out, TOK_, C_, HID_);
}